// round 1
// baseline (speedup 1.0000x reference)
#include <cuda_runtime.h>
#include <math.h>

// ---------------- problem constants ----------------
#define BB   2
#define LL   2048
#define DM   1024
#define DI   2048
#define DTR  64
#define DS   16
#define MTOK (BB * LL)   // 4096 tokens
#define XDBL_W 96        // DT_RANK + 2*D_STATE

// ---------------- scratch (static device globals; no runtime alloc) -------
__device__ float g_xn   [(size_t)MTOK * DM];      // 16 MB
__device__ float g_xz   [(size_t)MTOK * 2 * DI];  // 64 MB  (u | z)
__device__ float g_uconv[(size_t)MTOK * DI];      // 32 MB
__device__ float g_xdbl [(size_t)MTOK * XDBL_W];  // 1.5 MB
__device__ float g_delta[(size_t)MTOK * DI];      // 32 MB
__device__ float g_y    [(size_t)MTOK * DI];      // 32 MB

// ---------------- helpers ----------------
__device__ __forceinline__ float softplus_f(float v) {
    return (v > 20.f) ? v : log1pf(__expf(v));
}
__device__ __forceinline__ float silu_f(float v) {
    return v * (1.f / (1.f + __expf(-v)));
}

// ---------------- LayerNorm: one block (256 thr) per token row of 1024 ----
__global__ void ln_kernel(const float* __restrict__ x,
                          const float* __restrict__ w,
                          const float* __restrict__ b,
                          float* __restrict__ out) {
    const int row = blockIdx.x;
    const int tid = threadIdx.x;            // 0..255, DM/4 == 256
    const float4* xr = (const float4*)(x + (size_t)row * DM);
    float4 v = xr[tid];

    float s  = v.x + v.y + v.z + v.w;
    float s2 = v.x * v.x + v.y * v.y + v.z * v.z + v.w * v.w;

    __shared__ float shs[8], shs2[8];
    #pragma unroll
    for (int o = 16; o > 0; o >>= 1) {
        s  += __shfl_down_sync(0xffffffffu, s,  o);
        s2 += __shfl_down_sync(0xffffffffu, s2, o);
    }
    if ((tid & 31) == 0) { shs[tid >> 5] = s; shs2[tid >> 5] = s2; }
    __syncthreads();
    float mu = 0.f, m2 = 0.f;
    #pragma unroll
    for (int i = 0; i < 8; i++) { mu += shs[i]; m2 += shs2[i]; }
    mu *= (1.f / DM);
    m2 *= (1.f / DM);
    float var = m2 - mu * mu;
    float inv = rsqrtf(var + 1e-5f);

    float4 wv = ((const float4*)w)[tid];
    float4 bv = ((const float4*)b)[tid];
    float4 o;
    o.x = (v.x - mu) * inv * wv.x + bv.x;
    o.y = (v.y - mu) * inv * wv.y + bv.y;
    o.z = (v.z - mu) * inv * wv.z + bv.z;
    o.w = (v.w - mu) * inv * wv.w + bv.w;
    ((float4*)(out + (size_t)row * DM))[tid] = o;
}

// ---------------- generic tiled fp32 GEMM:  C[m,n] = dot(A[m,:], W[n,:]) ----
// A: M x K row-major (lda), W: N x K row-major (ldw = K), C: M x N (ldc).
// EPI: 0 = none, 1 = softplus(v + aux[n]), 2 = v + aux[m*ldc + n] (residual)
template<int BM, int BN, int BK, int TM, int TN, int EPI>
__global__ void gemm_kernel(const float* __restrict__ A, int lda,
                            const float* __restrict__ W,
                            float* __restrict__ C, int ldc,
                            int M, int N, int K,
                            const float* __restrict__ aux) {
    constexpr int NT = (BM / TM) * (BN / TN);
    __shared__ float As[BK][BM];
    __shared__ float Ws[BK][BN];

    const int tid = threadIdx.x;
    const int bm0 = blockIdx.y * BM;
    const int bn0 = blockIdx.x * BN;

    const int tm0 = (tid / (BN / TN)) * TM;
    const int tn0 = (tid % (BN / TN)) * TN;

    float acc[TM][TN];
    #pragma unroll
    for (int i = 0; i < TM; i++)
        #pragma unroll
        for (int j = 0; j < TN; j++) acc[i][j] = 0.f;

    for (int k0 = 0; k0 < K; k0 += BK) {
        // load A tile (M assumed multiple of BM; K multiple of BK; 16B aligned)
        for (int idx = tid; idx < BM * BK / 4; idx += NT) {
            int r  = idx / (BK / 4);
            int c4 = (idx % (BK / 4)) * 4;
            float4 v = *(const float4*)(A + (size_t)(bm0 + r) * lda + k0 + c4);
            As[c4 + 0][r] = v.x; As[c4 + 1][r] = v.y;
            As[c4 + 2][r] = v.z; As[c4 + 3][r] = v.w;
        }
        // load W tile (guard N)
        for (int idx = tid; idx < BN * BK / 4; idx += NT) {
            int r  = idx / (BK / 4);
            int c4 = (idx % (BK / 4)) * 4;
            int gn = bn0 + r;
            float4 v = make_float4(0.f, 0.f, 0.f, 0.f);
            if (gn < N) v = *(const float4*)(W + (size_t)gn * K + k0 + c4);
            Ws[c4 + 0][r] = v.x; Ws[c4 + 1][r] = v.y;
            Ws[c4 + 2][r] = v.z; Ws[c4 + 3][r] = v.w;
        }
        __syncthreads();

        #pragma unroll
        for (int k = 0; k < BK; k++) {
            float am[TM], wn[TN];
            #pragma unroll
            for (int i = 0; i < TM; i++) am[i] = As[k][tm0 + i];
            #pragma unroll
            for (int j = 0; j < TN; j++) wn[j] = Ws[k][tn0 + j];
            #pragma unroll
            for (int i = 0; i < TM; i++)
                #pragma unroll
                for (int j = 0; j < TN; j++)
                    acc[i][j] = fmaf(am[i], wn[j], acc[i][j]);
        }
        __syncthreads();
    }

    #pragma unroll
    for (int i = 0; i < TM; i++) {
        int gm = bm0 + tm0 + i;
        #pragma unroll
        for (int j = 0; j < TN; j++) {
            int gn = bn0 + tn0 + j;
            if (gn < N) {
                float v = acc[i][j];
                if (EPI == 1) v = softplus_f(v + aux[gn]);
                if (EPI == 2) v = v + aux[(size_t)gm * ldc + gn];
                C[(size_t)gm * ldc + gn] = v;
            }
        }
    }
}

// ---------------- causal depthwise conv (width 4) + bias + SiLU -----------
// reads u part of xz (stride 2*DI), writes uconv (stride DI)
__global__ void conv_silu_kernel(const float* __restrict__ xz,
                                 const float* __restrict__ cw,
                                 const float* __restrict__ cb,
                                 float* __restrict__ out) {
    int idx = blockIdx.x * blockDim.x + threadIdx.x;
    if (idx >= MTOK * DI) return;
    int d = idx % DI;
    int t = idx / DI;         // global token = b*L + l
    int l = t % LL;

    float w0 = cw[d * 4 + 0], w1 = cw[d * 4 + 1];
    float w2 = cw[d * 4 + 2], w3 = cw[d * 4 + 3];
    const float* up = xz + (size_t)t * (2 * DI) + d;

    float acc = w3 * up[0];
    if (l >= 1) acc += w2 * up[-(ptrdiff_t)(2 * DI) * 1];
    if (l >= 2) acc += w1 * up[-(ptrdiff_t)(2 * DI) * 2];
    if (l >= 3) acc += w0 * up[-(ptrdiff_t)(2 * DI) * 3];
    acc += cb[d];
    out[idx] = silu_f(acc);
}

// ---------------- selective scan ------------------------------------------
// half-warp (16 lanes) per (b, d): lane n owns state n. Sequential over L.
// Fuses D-skip and SiLU(z) gate. Output y (MTOK x DI).
__global__ void scan_kernel(const float* __restrict__ delta,
                            const float* __restrict__ u,
                            const float* __restrict__ xdbl,
                            const float* __restrict__ xz,
                            const float* __restrict__ A_log,
                            const float* __restrict__ Dp,
                            float* __restrict__ y) {
    int gt   = blockIdx.x * blockDim.x + threadIdx.x;
    int w    = gt >> 5;                 // warp id: 0 .. BB*DI/2-1  (2048)
    int lane = gt & 31;
    if (w >= BB * (DI / 2)) return;

    int b    = w >> 10;                 // DI/2 == 1024 pairs per batch
    int pair = w & 1023;
    int dd   = pair * 2 + (lane >> 4);  // channel handled by this half-warp
    int n    = lane & 15;               // state index

    float Ad = -expf(A_log[dd * DS + n]);
    float Dd = Dp[dd];
    float h  = 0.f;

    size_t rowd = (size_t)b * LL * DI + dd;       // += DI per step
    size_t rowx = (size_t)b * LL * XDBL_W;        // += 96 per step
    size_t rowz = ((size_t)b * LL) * (2 * DI) + DI + dd;  // z part of xz

    for (int t = 0; t < LL; t++) {
        float de = delta[rowd];
        float uu = u[rowd];
        float Bn = xdbl[rowx + DTR + n];
        float Cn = xdbl[rowx + DTR + DS + n];

        float dA = __expf(de * Ad);
        h = fmaf(dA, h, de * uu * Bn);

        float yv = h * Cn;
        yv += __shfl_xor_sync(0xffffffffu, yv, 8);
        yv += __shfl_xor_sync(0xffffffffu, yv, 4);
        yv += __shfl_xor_sync(0xffffffffu, yv, 2);
        yv += __shfl_xor_sync(0xffffffffu, yv, 1);

        if (n == 0) {
            float zv = xz[rowz];
            y[rowd] = (yv + uu * Dd) * silu_f(zv);
        }
        rowd += DI;
        rowx += XDBL_W;
        rowz += 2 * DI;
    }
}

// ---------------- launch ----------------------------------------------------
extern "C" void kernel_launch(void* const* d_in, const int* in_sizes, int n_in,
                              void* d_out, int out_size) {
    const float* x         = (const float*)d_in[0];
    const float* ln_w      = (const float*)d_in[1];
    const float* ln_b      = (const float*)d_in[2];
    const float* in_proj_w = (const float*)d_in[3];
    const float* conv_w    = (const float*)d_in[4];
    const float* conv_b    = (const float*)d_in[5];
    const float* x_proj_w  = (const float*)d_in[6];
    const float* dt_proj_w = (const float*)d_in[7];
    const float* dt_proj_b = (const float*)d_in[8];
    const float* A_log     = (const float*)d_in[9];
    const float* Dp        = (const float*)d_in[10];
    const float* out_pw    = (const float*)d_in[11];
    float* out = (float*)d_out;

    float *xn, *xz, *uconv, *xdbl, *delta, *y;
    cudaGetSymbolAddress((void**)&xn,    g_xn);
    cudaGetSymbolAddress((void**)&xz,    g_xz);
    cudaGetSymbolAddress((void**)&uconv, g_uconv);
    cudaGetSymbolAddress((void**)&xdbl,  g_xdbl);
    cudaGetSymbolAddress((void**)&delta, g_delta);
    cudaGetSymbolAddress((void**)&y,     g_y);

    // 1. LayerNorm
    ln_kernel<<<MTOK, 256>>>(x, ln_w, ln_b, xn);

    // 2. in_proj: xn(4096x1024) @ W(4096x1024)^T -> xz(4096x4096)
    gemm_kernel<128, 128, 16, 8, 8, 0><<<dim3(32, 32), 256>>>(
        xn, DM, in_proj_w, xz, 2 * DI, MTOK, 2 * DI, DM, nullptr);

    // 3. causal conv + SiLU -> uconv
    conv_silu_kernel<<<(MTOK * DI + 255) / 256, 256>>>(xz, conv_w, conv_b, uconv);

    // 4. x_proj: uconv(4096x2048) @ W(96x2048)^T -> xdbl(4096x96)
    gemm_kernel<64, 96, 16, 4, 6, 0><<<dim3(1, MTOK / 64), 256>>>(
        uconv, DI, x_proj_w, xdbl, XDBL_W, MTOK, XDBL_W, DI, nullptr);

    // 5. dt_proj: xdbl[:, :64](lda=96) @ W(2048x64)^T, +bias, softplus -> delta
    gemm_kernel<128, 128, 16, 8, 8, 1><<<dim3(DI / 128, MTOK / 128), 256>>>(
        xdbl, XDBL_W, dt_proj_w, delta, DI, MTOK, DI, DTR, dt_proj_b);

    // 6. selective scan (+D skip, +SiLU(z) gate) -> y
    scan_kernel<<<(BB * (DI / 2) * 32) / 128, 128>>>(
        delta, uconv, xdbl, xz, A_log, Dp, y);

    // 7. out_proj: y(4096x2048) @ W(1024x2048)^T + x residual -> out
    gemm_kernel<128, 128, 16, 8, 8, 2><<<dim3(DM / 128, MTOK / 128), 256>>>(
        y, DI, out_pw, out, DM, MTOK, DM, DI, x);
}

// round 2
// speedup vs baseline: 1.4980x; 1.4980x over previous
#include <cuda_runtime.h>
#include <math.h>
#include <stdint.h>

// ---------------- problem constants ----------------
#define BB   2
#define LL   2048
#define DM   1024
#define DI   2048
#define DTR  64
#define DS   16
#define MTOK (BB * LL)   // 4096 tokens
#define XDBL_W 96        // DT_RANK + 2*D_STATE

// ---------------- scratch (static device globals; no runtime alloc) -------
__device__ float g_xn   [(size_t)MTOK * DM];
__device__ float g_xz   [(size_t)MTOK * 2 * DI];
__device__ float g_uconv[(size_t)MTOK * DI];
__device__ float g_xdbl [(size_t)MTOK * XDBL_W];
__device__ float g_delta[(size_t)MTOK * DI];
__device__ float g_y    [(size_t)MTOK * DI];

// ---------------- helpers ----------------
__device__ __forceinline__ float softplus_f(float v) {
    return (v > 20.f) ? v : log1pf(__expf(v));
}
__device__ __forceinline__ float silu_f(float v) {
    return v * (1.f / (1.f + __expf(-v)));
}
__device__ __forceinline__ uint32_t to_tf32(float f) {
    uint32_t r;
    asm("cvt.rna.tf32.f32 %0, %1;" : "=r"(r) : "f"(f));
    return r;
}
__device__ __forceinline__ void mma_tf32(float* c, const uint32_t* a, const uint32_t* b) {
    asm volatile("mma.sync.aligned.m16n8k8.row.col.f32.tf32.tf32.f32 "
                 "{%0,%1,%2,%3}, {%4,%5,%6,%7}, {%8,%9}, {%0,%1,%2,%3};"
                 : "+f"(c[0]), "+f"(c[1]), "+f"(c[2]), "+f"(c[3])
                 : "r"(a[0]), "r"(a[1]), "r"(a[2]), "r"(a[3]),
                   "r"(b[0]), "r"(b[1]));
}
__device__ __forceinline__ void cp16(void* dst, const void* src) {
    uint32_t d = (uint32_t)__cvta_generic_to_shared(dst);
    asm volatile("cp.async.cg.shared.global [%0], [%1], 16;" :: "r"(d), "l"(src));
}

// ---------------- LayerNorm ----------------
__global__ void ln_kernel(const float* __restrict__ x,
                          const float* __restrict__ w,
                          const float* __restrict__ b,
                          float* __restrict__ out) {
    const int row = blockIdx.x;
    const int tid = threadIdx.x;            // 0..255, DM/4 == 256
    const float4* xr = (const float4*)(x + (size_t)row * DM);
    float4 v = xr[tid];

    float s  = v.x + v.y + v.z + v.w;
    float s2 = v.x * v.x + v.y * v.y + v.z * v.z + v.w * v.w;

    __shared__ float shs[8], shs2[8];
    #pragma unroll
    for (int o = 16; o > 0; o >>= 1) {
        s  += __shfl_down_sync(0xffffffffu, s,  o);
        s2 += __shfl_down_sync(0xffffffffu, s2, o);
    }
    if ((tid & 31) == 0) { shs[tid >> 5] = s; shs2[tid >> 5] = s2; }
    __syncthreads();
    float mu = 0.f, m2 = 0.f;
    #pragma unroll
    for (int i = 0; i < 8; i++) { mu += shs[i]; m2 += shs2[i]; }
    mu *= (1.f / DM);
    m2 *= (1.f / DM);
    float var = m2 - mu * mu;
    float inv = rsqrtf(var + 1e-5f);

    float4 wv = ((const float4*)w)[tid];
    float4 bv = ((const float4*)b)[tid];
    float4 o;
    o.x = (v.x - mu) * inv * wv.x + bv.x;
    o.y = (v.y - mu) * inv * wv.y + bv.y;
    o.z = (v.z - mu) * inv * wv.z + bv.z;
    o.w = (v.w - mu) * inv * wv.w + bv.w;
    ((float4*)(out + (size_t)row * DM))[tid] = o;
}

// ---------------- tf32 tensor-core GEMM ------------------------------------
// C[M,N] = A[M,K] @ W[N,K]^T.  A row-major (lda), W row-major (ldw), C (ldc).
// BK=16 k-tile, cp.async double-buffered. 8 warps: WM x WN layout; each warp
// computes (BM/WM) x (BN/WN) via m16n8k8 tf32 mma.
// Requires: M % BM == 0, N % BN == 0, K % 16 == 0, pointers 16B aligned.
// EPI: 0 none, 1 softplus(v + aux[n]), 2 v + aux[m*ldc + n]
template<int BM, int BN, int WM, int WN, int EPI>
__global__ __launch_bounds__(WM * WN * 32)
void gemm_tc(const float* __restrict__ A, int lda,
             const float* __restrict__ W, int ldw,
             float* __restrict__ C, int ldc,
             int K, const float* __restrict__ aux) {
    constexpr int NTHR = WM * WN * 32;
    constexpr int BKP = 20;               // 16 + 4 pad: conflict-free frag loads
    constexpr int WARP_M = BM / WM;
    constexpr int WARP_N = BN / WN;
    constexpr int MT = WARP_M / 16;
    constexpr int NT = WARP_N / 8;

    __shared__ __align__(16) float As[2][BM][BKP];
    __shared__ __align__(16) float Bs[2][BN][BKP];

    const int tid  = threadIdx.x;
    const int lane = tid & 31;
    const int warp = tid >> 5;
    const int gid  = lane >> 2;            // 0..7
    const int tig  = lane & 3;             // 0..3

    const int bm0 = blockIdx.y * BM;
    const int bn0 = blockIdx.x * BN;
    const int wm0 = (warp / WN) * WARP_M;
    const int wn0 = (warp % WN) * WARP_N;

    float acc[MT][NT][4];
    #pragma unroll
    for (int i = 0; i < MT; i++)
        #pragma unroll
        for (int j = 0; j < NT; j++)
            #pragma unroll
            for (int e = 0; e < 4; e++) acc[i][j][e] = 0.f;

    // tile loader (issues cp.async + commit)
    auto load_tile = [&](int buf, int k0) {
        #pragma unroll 2
        for (int s = tid; s < BM * 4; s += NTHR) {
            int r = s >> 2, c = (s & 3) * 4;
            cp16(&As[buf][r][c], A + (size_t)(bm0 + r) * lda + k0 + c);
        }
        #pragma unroll 2
        for (int s = tid; s < BN * 4; s += NTHR) {
            int r = s >> 2, c = (s & 3) * 4;
            cp16(&Bs[buf][r][c], W + (size_t)(bn0 + r) * ldw + k0 + c);
        }
        asm volatile("cp.async.commit_group;");
    };

    load_tile(0, 0);
    const int nkt = K / 16;

    for (int kt = 0; kt < nkt; kt++) {
        const int buf = kt & 1;
        if (kt + 1 < nkt) {
            load_tile((kt + 1) & 1, (kt + 1) * 16);
            asm volatile("cp.async.wait_group 1;");
        } else {
            asm volatile("cp.async.wait_group 0;");
        }
        __syncthreads();

        #pragma unroll
        for (int k8 = 0; k8 < 2; k8++) {
            const int k0 = k8 * 8;
            uint32_t af[MT][4];
            uint32_t bf[NT][2];
            #pragma unroll
            for (int mt = 0; mt < MT; mt++) {
                int r = wm0 + mt * 16;
                af[mt][0] = to_tf32(As[buf][r + gid    ][k0 + tig    ]);
                af[mt][1] = to_tf32(As[buf][r + gid + 8][k0 + tig    ]);
                af[mt][2] = to_tf32(As[buf][r + gid    ][k0 + tig + 4]);
                af[mt][3] = to_tf32(As[buf][r + gid + 8][k0 + tig + 4]);
            }
            #pragma unroll
            for (int nt = 0; nt < NT; nt++) {
                int cNb = wn0 + nt * 8;
                bf[nt][0] = to_tf32(Bs[buf][cNb + gid][k0 + tig    ]);
                bf[nt][1] = to_tf32(Bs[buf][cNb + gid][k0 + tig + 4]);
            }
            #pragma unroll
            for (int mt = 0; mt < MT; mt++)
                #pragma unroll
                for (int nt = 0; nt < NT; nt++)
                    mma_tf32(acc[mt][nt], af[mt], bf[nt]);
        }
        __syncthreads();
    }

    // epilogue
    #pragma unroll
    for (int mt = 0; mt < MT; mt++) {
        int r0 = bm0 + wm0 + mt * 16 + gid;
        int r1 = r0 + 8;
        #pragma unroll
        for (int nt = 0; nt < NT; nt++) {
            int cn = bn0 + wn0 + nt * 8 + 2 * tig;
            float v0 = acc[mt][nt][0], v1 = acc[mt][nt][1];
            float v2 = acc[mt][nt][2], v3 = acc[mt][nt][3];
            if (EPI == 1) {
                v0 = softplus_f(v0 + aux[cn]);   v1 = softplus_f(v1 + aux[cn + 1]);
                v2 = softplus_f(v2 + aux[cn]);   v3 = softplus_f(v3 + aux[cn + 1]);
            }
            if (EPI == 2) {
                v0 += aux[(size_t)r0 * ldc + cn];     v1 += aux[(size_t)r0 * ldc + cn + 1];
                v2 += aux[(size_t)r1 * ldc + cn];     v3 += aux[(size_t)r1 * ldc + cn + 1];
            }
            *(float2*)(C + (size_t)r0 * ldc + cn) = make_float2(v0, v1);
            *(float2*)(C + (size_t)r1 * ldc + cn) = make_float2(v2, v3);
        }
    }
}

// ---------------- causal depthwise conv (width 4) + bias + SiLU -----------
__global__ void conv_silu_kernel(const float* __restrict__ xz,
                                 const float* __restrict__ cw,
                                 const float* __restrict__ cb,
                                 float* __restrict__ out) {
    int idx = blockIdx.x * blockDim.x + threadIdx.x;
    if (idx >= MTOK * DI) return;
    int d = idx % DI;
    int t = idx / DI;
    int l = t % LL;

    float w0 = cw[d * 4 + 0], w1 = cw[d * 4 + 1];
    float w2 = cw[d * 4 + 2], w3 = cw[d * 4 + 3];
    const float* up = xz + (size_t)t * (2 * DI) + d;

    float acc = w3 * up[0];
    if (l >= 1) acc += w2 * up[-(ptrdiff_t)(2 * DI) * 1];
    if (l >= 2) acc += w1 * up[-(ptrdiff_t)(2 * DI) * 2];
    if (l >= 3) acc += w0 * up[-(ptrdiff_t)(2 * DI) * 3];
    acc += cb[d];
    out[idx] = silu_f(acc);
}

// ---------------- selective scan ------------------------------------------
__global__ void scan_kernel(const float* __restrict__ delta,
                            const float* __restrict__ u,
                            const float* __restrict__ xdbl,
                            const float* __restrict__ xz,
                            const float* __restrict__ A_log,
                            const float* __restrict__ Dp,
                            float* __restrict__ y) {
    int gt   = blockIdx.x * blockDim.x + threadIdx.x;
    int w    = gt >> 5;
    int lane = gt & 31;
    if (w >= BB * (DI / 2)) return;

    int b    = w >> 10;
    int pair = w & 1023;
    int dd   = pair * 2 + (lane >> 4);
    int n    = lane & 15;

    float Ad = -expf(A_log[dd * DS + n]);
    float Dd = Dp[dd];
    float h  = 0.f;

    size_t rowd = (size_t)b * LL * DI + dd;
    size_t rowx = (size_t)b * LL * XDBL_W;
    size_t rowz = ((size_t)b * LL) * (2 * DI) + DI + dd;

    for (int t = 0; t < LL; t++) {
        float de = delta[rowd];
        float uu = u[rowd];
        float Bn = xdbl[rowx + DTR + n];
        float Cn = xdbl[rowx + DTR + DS + n];

        float dA = __expf(de * Ad);
        h = fmaf(dA, h, de * uu * Bn);

        float yv = h * Cn;
        yv += __shfl_xor_sync(0xffffffffu, yv, 8);
        yv += __shfl_xor_sync(0xffffffffu, yv, 4);
        yv += __shfl_xor_sync(0xffffffffu, yv, 2);
        yv += __shfl_xor_sync(0xffffffffu, yv, 1);

        if (n == 0) {
            float zv = xz[rowz];
            y[rowd] = (yv + uu * Dd) * silu_f(zv);
        }
        rowd += DI;
        rowx += XDBL_W;
        rowz += 2 * DI;
    }
}

// ---------------- launch ----------------------------------------------------
extern "C" void kernel_launch(void* const* d_in, const int* in_sizes, int n_in,
                              void* d_out, int out_size) {
    const float* x         = (const float*)d_in[0];
    const float* ln_w      = (const float*)d_in[1];
    const float* ln_b      = (const float*)d_in[2];
    const float* in_proj_w = (const float*)d_in[3];
    const float* conv_w    = (const float*)d_in[4];
    const float* conv_b    = (const float*)d_in[5];
    const float* x_proj_w  = (const float*)d_in[6];
    const float* dt_proj_w = (const float*)d_in[7];
    const float* dt_proj_b = (const float*)d_in[8];
    const float* A_log     = (const float*)d_in[9];
    const float* Dp        = (const float*)d_in[10];
    const float* out_pw    = (const float*)d_in[11];
    float* out = (float*)d_out;

    float *xn, *xz, *uconv, *xdbl, *delta, *y;
    cudaGetSymbolAddress((void**)&xn,    g_xn);
    cudaGetSymbolAddress((void**)&xz,    g_xz);
    cudaGetSymbolAddress((void**)&uconv, g_uconv);
    cudaGetSymbolAddress((void**)&xdbl,  g_xdbl);
    cudaGetSymbolAddress((void**)&delta, g_delta);
    cudaGetSymbolAddress((void**)&y,     g_y);

    // 1. LayerNorm
    ln_kernel<<<MTOK, 256>>>(x, ln_w, ln_b, xn);

    // 2. in_proj: xn(4096x1024) @ W(4096x1024)^T -> xz(4096x4096)
    gemm_tc<128, 128, 2, 4, 0><<<dim3((2 * DI) / 128, MTOK / 128), 256>>>(
        xn, DM, in_proj_w, DM, xz, 2 * DI, DM, nullptr);

    // 3. causal conv + SiLU -> uconv
    conv_silu_kernel<<<(MTOK * DI + 255) / 256, 256>>>(xz, conv_w, conv_b, uconv);

    // 4. x_proj: uconv(4096x2048) @ W(96x2048)^T -> xdbl(4096x96)
    gemm_tc<64, 96, 2, 4, 0><<<dim3(1, MTOK / 64), 256>>>(
        uconv, DI, x_proj_w, DI, xdbl, XDBL_W, DI, nullptr);

    // 5. dt_proj: xdbl[:, :64](lda=96) @ W(2048x64)^T, +bias, softplus -> delta
    gemm_tc<128, 128, 2, 4, 1><<<dim3(DI / 128, MTOK / 128), 256>>>(
        xdbl, XDBL_W, dt_proj_w, DTR, delta, DI, DTR, dt_proj_b);

    // 6. selective scan (+D skip, +SiLU(z) gate) -> y
    scan_kernel<<<(BB * (DI / 2) * 32) / 128, 128>>>(
        delta, uconv, xdbl, xz, A_log, Dp, y);

    // 7. out_proj: y(4096x2048) @ W(1024x2048)^T + x residual -> out
    gemm_tc<128, 128, 2, 4, 2><<<dim3(DM / 128, MTOK / 128), 256>>>(
        y, DI, out_pw, DI, out, DM, DI, x);
}

// round 3
// speedup vs baseline: 4.2501x; 2.8371x over previous
#include <cuda_runtime.h>
#include <math.h>
#include <stdint.h>

// ---------------- problem constants ----------------
#define BB   2
#define LL   2048
#define DM   1024
#define DI   2048
#define DTR  64
#define DS   16
#define MTOK (BB * LL)   // 4096 tokens
#define XDBL_W 96        // DT_RANK + 2*D_STATE

// ---------------- scratch (static device globals; no runtime alloc) -------
__device__ float g_xn   [(size_t)MTOK * DM];
__device__ float g_xz   [(size_t)MTOK * 2 * DI];
__device__ float g_uconv[(size_t)MTOK * DI];
__device__ float g_xdbl [(size_t)MTOK * XDBL_W];
__device__ float g_delta[(size_t)MTOK * DI];
__device__ float g_y    [(size_t)MTOK * DI];

// ---------------- helpers ----------------
__device__ __forceinline__ float softplus_f(float v) {
    return (v > 20.f) ? v : log1pf(__expf(v));
}
__device__ __forceinline__ float silu_f(float v) {
    return v * (1.f / (1.f + __expf(-v)));
}
__device__ __forceinline__ void mma_tf32(float* c, const uint32_t* a, const uint32_t* b) {
    asm volatile("mma.sync.aligned.m16n8k8.row.col.f32.tf32.tf32.f32 "
                 "{%0,%1,%2,%3}, {%4,%5,%6,%7}, {%8,%9}, {%0,%1,%2,%3};"
                 : "+f"(c[0]), "+f"(c[1]), "+f"(c[2]), "+f"(c[3])
                 : "r"(a[0]), "r"(a[1]), "r"(a[2]), "r"(a[3]),
                   "r"(b[0]), "r"(b[1]));
}
__device__ __forceinline__ void cp16(void* dst, const void* src) {
    uint32_t d = (uint32_t)__cvta_generic_to_shared(dst);
    asm volatile("cp.async.cg.shared.global [%0], [%1], 16;" :: "r"(d), "l"(src));
}

// ---------------- LayerNorm ----------------
__global__ void ln_kernel(const float* __restrict__ x,
                          const float* __restrict__ w,
                          const float* __restrict__ b,
                          float* __restrict__ out) {
    const int row = blockIdx.x;
    const int tid = threadIdx.x;            // 0..255, DM/4 == 256
    const float4* xr = (const float4*)(x + (size_t)row * DM);
    float4 v = xr[tid];

    float s  = v.x + v.y + v.z + v.w;
    float s2 = v.x * v.x + v.y * v.y + v.z * v.z + v.w * v.w;

    __shared__ float shs[8], shs2[8];
    #pragma unroll
    for (int o = 16; o > 0; o >>= 1) {
        s  += __shfl_down_sync(0xffffffffu, s,  o);
        s2 += __shfl_down_sync(0xffffffffu, s2, o);
    }
    if ((tid & 31) == 0) { shs[tid >> 5] = s; shs2[tid >> 5] = s2; }
    __syncthreads();
    float mu = 0.f, m2 = 0.f;
    #pragma unroll
    for (int i = 0; i < 8; i++) { mu += shs[i]; m2 += shs2[i]; }
    mu *= (1.f / DM);
    m2 *= (1.f / DM);
    float var = m2 - mu * mu;
    float inv = rsqrtf(var + 1e-5f);

    float4 wv = ((const float4*)w)[tid];
    float4 bv = ((const float4*)b)[tid];
    float4 o;
    o.x = (v.x - mu) * inv * wv.x + bv.x;
    o.y = (v.y - mu) * inv * wv.y + bv.y;
    o.z = (v.z - mu) * inv * wv.z + bv.z;
    o.w = (v.w - mu) * inv * wv.w + bv.w;
    ((float4*)(out + (size_t)row * DM))[tid] = o;
}

// ---------------- tf32 tensor-core GEMM ------------------------------------
// C[M,N] = A[M,K] @ W[N,K]^T. No cvt: fp32 bits fed to tf32 mma (HW truncates).
// BK=16 k-tile, cp.async double-buffered. Both k8 fragment sets loaded before
// any mma so LDS latency hides behind the tensor pipe.
// EPI: 0 none, 1 softplus(v + aux[n]), 2 v + aux[m*ldc + n]
template<int BM, int BN, int WM, int WN, int EPI>
__global__ __launch_bounds__(WM * WN * 32)
void gemm_tc(const float* __restrict__ A, int lda,
             const float* __restrict__ W, int ldw,
             float* __restrict__ C, int ldc,
             int K, const float* __restrict__ aux) {
    constexpr int NTHR = WM * WN * 32;
    constexpr int BKP = 20;               // 16 + 4 pad: conflict-free frag loads
    constexpr int WARP_M = BM / WM;
    constexpr int WARP_N = BN / WN;
    constexpr int MT = WARP_M / 16;
    constexpr int NT = WARP_N / 8;

    __shared__ __align__(16) uint32_t As[2][BM][BKP];
    __shared__ __align__(16) uint32_t Bs[2][BN][BKP];

    const int tid  = threadIdx.x;
    const int lane = tid & 31;
    const int warp = tid >> 5;
    const int gid  = lane >> 2;            // 0..7
    const int tig  = lane & 3;             // 0..3

    const int bm0 = blockIdx.y * BM;
    const int bn0 = blockIdx.x * BN;
    const int wm0 = (warp / WN) * WARP_M;
    const int wn0 = (warp % WN) * WARP_N;

    float acc[MT][NT][4];
    #pragma unroll
    for (int i = 0; i < MT; i++)
        #pragma unroll
        for (int j = 0; j < NT; j++)
            #pragma unroll
            for (int e = 0; e < 4; e++) acc[i][j][e] = 0.f;

    auto load_tile = [&](int buf, int k0) {
        #pragma unroll 2
        for (int s = tid; s < BM * 4; s += NTHR) {
            int r = s >> 2, c = (s & 3) * 4;
            cp16(&As[buf][r][c], A + (size_t)(bm0 + r) * lda + k0 + c);
        }
        #pragma unroll 2
        for (int s = tid; s < BN * 4; s += NTHR) {
            int r = s >> 2, c = (s & 3) * 4;
            cp16(&Bs[buf][r][c], W + (size_t)(bn0 + r) * ldw + k0 + c);
        }
        asm volatile("cp.async.commit_group;");
    };

    load_tile(0, 0);
    const int nkt = K / 16;

    for (int kt = 0; kt < nkt; kt++) {
        const int buf = kt & 1;
        if (kt + 1 < nkt) {
            load_tile((kt + 1) & 1, (kt + 1) * 16);
            asm volatile("cp.async.wait_group 1;");
        } else {
            asm volatile("cp.async.wait_group 0;");
        }
        __syncthreads();

        // load ALL fragments (both k8 halves) before any mma
        uint32_t af[2][MT][4];
        uint32_t bf[2][NT][2];
        #pragma unroll
        for (int k8 = 0; k8 < 2; k8++) {
            const int k0 = k8 * 8;
            #pragma unroll
            for (int mt = 0; mt < MT; mt++) {
                int r = wm0 + mt * 16;
                af[k8][mt][0] = As[buf][r + gid    ][k0 + tig    ];
                af[k8][mt][1] = As[buf][r + gid + 8][k0 + tig    ];
                af[k8][mt][2] = As[buf][r + gid    ][k0 + tig + 4];
                af[k8][mt][3] = As[buf][r + gid + 8][k0 + tig + 4];
            }
            #pragma unroll
            for (int nt = 0; nt < NT; nt++) {
                int cNb = wn0 + nt * 8;
                bf[k8][nt][0] = Bs[buf][cNb + gid][k0 + tig    ];
                bf[k8][nt][1] = Bs[buf][cNb + gid][k0 + tig + 4];
            }
        }
        #pragma unroll
        for (int k8 = 0; k8 < 2; k8++)
            #pragma unroll
            for (int mt = 0; mt < MT; mt++)
                #pragma unroll
                for (int nt = 0; nt < NT; nt++)
                    mma_tf32(acc[mt][nt], af[k8][mt], bf[k8][nt]);
        __syncthreads();
    }

    // epilogue
    #pragma unroll
    for (int mt = 0; mt < MT; mt++) {
        int r0 = bm0 + wm0 + mt * 16 + gid;
        int r1 = r0 + 8;
        #pragma unroll
        for (int nt = 0; nt < NT; nt++) {
            int cn = bn0 + wn0 + nt * 8 + 2 * tig;
            float v0 = acc[mt][nt][0], v1 = acc[mt][nt][1];
            float v2 = acc[mt][nt][2], v3 = acc[mt][nt][3];
            if (EPI == 1) {
                v0 = softplus_f(v0 + aux[cn]);   v1 = softplus_f(v1 + aux[cn + 1]);
                v2 = softplus_f(v2 + aux[cn]);   v3 = softplus_f(v3 + aux[cn + 1]);
            }
            if (EPI == 2) {
                v0 += aux[(size_t)r0 * ldc + cn];     v1 += aux[(size_t)r0 * ldc + cn + 1];
                v2 += aux[(size_t)r1 * ldc + cn];     v3 += aux[(size_t)r1 * ldc + cn + 1];
            }
            *(float2*)(C + (size_t)r0 * ldc + cn) = make_float2(v0, v1);
            *(float2*)(C + (size_t)r1 * ldc + cn) = make_float2(v2, v3);
        }
    }
}

// ---------------- causal depthwise conv (width 4) + bias + SiLU -----------
__global__ void conv_silu_kernel(const float* __restrict__ xz,
                                 const float* __restrict__ cw,
                                 const float* __restrict__ cb,
                                 float* __restrict__ out) {
    int idx = blockIdx.x * blockDim.x + threadIdx.x;
    if (idx >= MTOK * DI) return;
    int d = idx % DI;
    int t = idx / DI;
    int l = t % LL;

    float w0 = cw[d * 4 + 0], w1 = cw[d * 4 + 1];
    float w2 = cw[d * 4 + 2], w3 = cw[d * 4 + 3];
    const float* up = xz + (size_t)t * (2 * DI) + d;

    float acc = w3 * up[0];
    if (l >= 1) acc += w2 * up[-(ptrdiff_t)(2 * DI) * 1];
    if (l >= 2) acc += w1 * up[-(ptrdiff_t)(2 * DI) * 2];
    if (l >= 3) acc += w0 * up[-(ptrdiff_t)(2 * DI) * 3];
    acc += cb[d];
    out[idx] = silu_f(acc);
}

// ---------------- selective scan: unroll-4, prefetched, interleaved shfl ---
__global__ void scan_kernel(const float* __restrict__ delta,
                            const float* __restrict__ u,
                            const float* __restrict__ xdbl,
                            const float* __restrict__ xz,
                            const float* __restrict__ A_log,
                            const float* __restrict__ Dp,
                            float* __restrict__ y) {
    int gt   = blockIdx.x * blockDim.x + threadIdx.x;
    int w    = gt >> 5;
    int lane = gt & 31;
    if (w >= BB * (DI / 2)) return;

    int b    = w >> 10;
    int pair = w & 1023;
    int dd   = pair * 2 + (lane >> 4);   // channel for this half-warp
    int n    = lane & 15;                // state index

    float Ad = -expf(A_log[dd * DS + n]);
    float Dd = Dp[dd];
    float h  = 0.f;

    const size_t base_d = (size_t)b * LL * DI + dd;
    const size_t base_x = (size_t)b * LL * XDBL_W;
    const size_t base_z = (size_t)b * LL * (2 * DI) + DI + dd;

    constexpr int U = 4;
    float de[U], uu[U], Bn[U], Cn[U], zv[U];
    #pragma unroll
    for (int j = 0; j < U; j++) {
        de[j] = delta[base_d + (size_t)j * DI];
        uu[j] = u    [base_d + (size_t)j * DI];
        Bn[j] = xdbl [base_x + (size_t)j * XDBL_W + DTR + n];
        Cn[j] = xdbl [base_x + (size_t)j * XDBL_W + DTR + DS + n];
        zv[j] = xz   [base_z + (size_t)j * (2 * DI)];
    }

    for (int t = 0; t < LL; t += U) {
        // stash current group
        float cde[U], cuu[U], cBn[U], cCn[U], czv[U];
        #pragma unroll
        for (int j = 0; j < U; j++) {
            cde[j] = de[j]; cuu[j] = uu[j]; cBn[j] = Bn[j];
            cCn[j] = Cn[j]; czv[j] = zv[j];
        }
        // prefetch next group (issues before the stall-heavy compute below)
        if (t + U < LL) {
            const size_t od = base_d + (size_t)(t + U) * DI;
            const size_t ox = base_x + (size_t)(t + U) * XDBL_W;
            const size_t oz = base_z + (size_t)(t + U) * (2 * DI);
            #pragma unroll
            for (int j = 0; j < U; j++) {
                de[j] = delta[od + (size_t)j * DI];
                uu[j] = u    [od + (size_t)j * DI];
                Bn[j] = xdbl [ox + (size_t)j * XDBL_W + DTR + n];
                Cn[j] = xdbl [ox + (size_t)j * XDBL_W + DTR + DS + n];
                zv[j] = xz   [oz + (size_t)j * (2 * DI)];
            }
        }
        // recurrence (serial chain is just 4 fma)
        float yv[U];
        #pragma unroll
        for (int j = 0; j < U; j++) {
            float dA = __expf(cde[j] * Ad);
            h = fmaf(dA, h, cde[j] * cuu[j] * cBn[j]);
            yv[j] = h * cCn[j];
        }
        // 4 interleaved reduction chains over the 16 state lanes
        #pragma unroll
        for (int o = 8; o > 0; o >>= 1) {
            #pragma unroll
            for (int j = 0; j < U; j++)
                yv[j] += __shfl_xor_sync(0xffffffffu, yv[j], o);
        }
        if (n == 0) {
            #pragma unroll
            for (int j = 0; j < U; j++)
                y[base_d + (size_t)(t + j) * DI] =
                    (yv[j] + cuu[j] * Dd) * silu_f(czv[j]);
        }
    }
}

// ---------------- launch ----------------------------------------------------
extern "C" void kernel_launch(void* const* d_in, const int* in_sizes, int n_in,
                              void* d_out, int out_size) {
    const float* x         = (const float*)d_in[0];
    const float* ln_w      = (const float*)d_in[1];
    const float* ln_b      = (const float*)d_in[2];
    const float* in_proj_w = (const float*)d_in[3];
    const float* conv_w    = (const float*)d_in[4];
    const float* conv_b    = (const float*)d_in[5];
    const float* x_proj_w  = (const float*)d_in[6];
    const float* dt_proj_w = (const float*)d_in[7];
    const float* dt_proj_b = (const float*)d_in[8];
    const float* A_log     = (const float*)d_in[9];
    const float* Dp        = (const float*)d_in[10];
    const float* out_pw    = (const float*)d_in[11];
    float* out = (float*)d_out;

    float *xn, *xz, *uconv, *xdbl, *delta, *y;
    cudaGetSymbolAddress((void**)&xn,    g_xn);
    cudaGetSymbolAddress((void**)&xz,    g_xz);
    cudaGetSymbolAddress((void**)&uconv, g_uconv);
    cudaGetSymbolAddress((void**)&xdbl,  g_xdbl);
    cudaGetSymbolAddress((void**)&delta, g_delta);
    cudaGetSymbolAddress((void**)&y,     g_y);

    // 1. LayerNorm
    ln_kernel<<<MTOK, 256>>>(x, ln_w, ln_b, xn);

    // 2. in_proj: xn(4096x1024) @ W(4096x1024)^T -> xz(4096x4096)
    gemm_tc<128, 128, 2, 4, 0><<<dim3((2 * DI) / 128, MTOK / 128), 256>>>(
        xn, DM, in_proj_w, DM, xz, 2 * DI, DM, nullptr);

    // 3. causal conv + SiLU -> uconv
    conv_silu_kernel<<<(MTOK * DI + 255) / 256, 256>>>(xz, conv_w, conv_b, uconv);

    // 4. x_proj: uconv(4096x2048) @ W(96x2048)^T -> xdbl(4096x96)  (128 CTAs)
    gemm_tc<32, 96, 2, 4, 0><<<dim3(1, MTOK / 32), 256>>>(
        uconv, DI, x_proj_w, DI, xdbl, XDBL_W, DI, nullptr);

    // 5. dt_proj: xdbl[:, :64](lda=96) @ W(2048x64)^T, +bias, softplus -> delta
    gemm_tc<128, 128, 2, 4, 1><<<dim3(DI / 128, MTOK / 128), 256>>>(
        xdbl, XDBL_W, dt_proj_w, DTR, delta, DI, DTR, dt_proj_b);

    // 6. selective scan (+D skip, +SiLU(z) gate) -> y
    scan_kernel<<<(BB * (DI / 2) * 32) / 128, 128>>>(
        delta, uconv, xdbl, xz, A_log, Dp, y);

    // 7. out_proj: y(4096x2048) @ W(1024x2048)^T + x residual -> out
    gemm_tc<128, 128, 2, 4, 2><<<dim3(DM / 128, MTOK / 128), 256>>>(
        y, DI, out_pw, DI, out, DM, DI, x);
}

// round 4
// speedup vs baseline: 5.5509x; 1.3061x over previous
#include <cuda_runtime.h>
#include <cuda_bf16.h>
#include <math.h>
#include <stdint.h>

// ---------------- problem constants ----------------
#define BB   2
#define LL   2048
#define DM   1024
#define DI   2048
#define DTR  64
#define DS   16
#define MTOK (BB * LL)   // 4096 tokens
#define XDBL_W 96

// ---------------- fp32 scratch ----------------
__device__ float g_xz   [(size_t)MTOK * 2 * DI];
__device__ float g_uconv[(size_t)MTOK * DI];
__device__ float g_xdbl [(size_t)MTOK * XDBL_W];
__device__ float g_delta[(size_t)MTOK * DI];
// ---------------- bf16 packed scratch (uint32 = 2 bf16) ----------------
__device__ uint32_t g_xn16   [(size_t)MTOK * DM / 2];
__device__ uint32_t g_uconv16[(size_t)MTOK * DI / 2];
__device__ uint32_t g_dt16   [(size_t)MTOK * DTR / 2];
__device__ __nv_bfloat16 g_y16[(size_t)MTOK * DI];
__device__ uint32_t g_win16  [(size_t)2 * DI * DM / 2];
__device__ uint32_t g_wx16   [(size_t)XDBL_W * DI / 2];
__device__ uint32_t g_wdt16  [(size_t)DI * DTR / 2];
__device__ uint32_t g_wout16 [(size_t)DM * DI / 2];

// ---------------- helpers ----------------
__device__ __forceinline__ float softplus_f(float v) {
    return (v > 20.f) ? v : log1pf(__expf(v));
}
__device__ __forceinline__ float silu_f(float v) {
    return v * (1.f / (1.f + __expf(-v)));
}
__device__ __forceinline__ uint32_t packbf(float lo, float hi) {
    __nv_bfloat162 h(__float2bfloat16_rn(lo), __float2bfloat16_rn(hi));
    return *reinterpret_cast<uint32_t*>(&h);
}
__device__ __forceinline__ void mma_bf16(float* c, const uint32_t* a, const uint32_t* b) {
    asm volatile("mma.sync.aligned.m16n8k16.row.col.f32.bf16.bf16.f32 "
                 "{%0,%1,%2,%3}, {%4,%5,%6,%7}, {%8,%9}, {%0,%1,%2,%3};"
                 : "+f"(c[0]), "+f"(c[1]), "+f"(c[2]), "+f"(c[3])
                 : "r"(a[0]), "r"(a[1]), "r"(a[2]), "r"(a[3]),
                   "r"(b[0]), "r"(b[1]));
}
__device__ __forceinline__ void cp16(void* dst, const void* src) {
    uint32_t d = (uint32_t)__cvta_generic_to_shared(dst);
    asm volatile("cp.async.cg.shared.global [%0], [%1], 16;" :: "r"(d), "l"(src));
}

// ---------------- fp32 -> packed bf16 convert (weights) ----------------
__global__ void f32_to_bf16x2(const float* __restrict__ src,
                              uint32_t* __restrict__ dst, int n2) {
    int i = blockIdx.x * blockDim.x + threadIdx.x;
    if (i < n2) {
        float2 v = ((const float2*)src)[i];
        dst[i] = packbf(v.x, v.y);
    }
}

// ---------------- LayerNorm -> bf16 packed output ----------------
__global__ void ln_kernel(const float* __restrict__ x,
                          const float* __restrict__ w,
                          const float* __restrict__ b,
                          uint32_t* __restrict__ out16) {
    const int row = blockIdx.x;
    const int tid = threadIdx.x;            // 0..255, DM/4 == 256
    const float4* xr = (const float4*)(x + (size_t)row * DM);
    float4 v = xr[tid];

    float s  = v.x + v.y + v.z + v.w;
    float s2 = v.x * v.x + v.y * v.y + v.z * v.z + v.w * v.w;

    __shared__ float shs[8], shs2[8];
    #pragma unroll
    for (int o = 16; o > 0; o >>= 1) {
        s  += __shfl_down_sync(0xffffffffu, s,  o);
        s2 += __shfl_down_sync(0xffffffffu, s2, o);
    }
    if ((tid & 31) == 0) { shs[tid >> 5] = s; shs2[tid >> 5] = s2; }
    __syncthreads();
    float mu = 0.f, m2 = 0.f;
    #pragma unroll
    for (int i = 0; i < 8; i++) { mu += shs[i]; m2 += shs2[i]; }
    mu *= (1.f / DM);
    m2 *= (1.f / DM);
    float var = m2 - mu * mu;
    float inv = rsqrtf(var + 1e-5f);

    float4 wv = ((const float4*)w)[tid];
    float4 bv = ((const float4*)b)[tid];
    float o0 = (v.x - mu) * inv * wv.x + bv.x;
    float o1 = (v.y - mu) * inv * wv.y + bv.y;
    float o2 = (v.z - mu) * inv * wv.z + bv.z;
    float o3 = (v.w - mu) * inv * wv.w + bv.w;
    uint2 p;
    p.x = packbf(o0, o1);
    p.y = packbf(o2, o3);
    ((uint2*)(out16 + (size_t)row * (DM / 2)))[tid] = p;
}

// ---------------- bf16 tensor-core GEMM -------------------------------------
// C[M,N] = A[M,K] @ W[N,K]^T. A,W packed bf16 (uint32 = 2 els), lda in uint32.
// BK=32, 3-stage cp.async pipeline, ONE __syncthreads per tile.
// EPI: 0 none, 1 softplus(v+aux[n]), 2 v+aux[m*ldc+n], 3 fp32 + bf16(dt cols)
template<int BM, int BN, int WM, int WN, int EPI>
__global__ __launch_bounds__(WM * WN * 32)
void gemm_bf16(const uint32_t* __restrict__ A, int ldaU,
               const uint32_t* __restrict__ W, int ldwU,
               float* __restrict__ C, int ldc, int K,
               const float* __restrict__ aux,
               uint32_t* __restrict__ Cb, int ldcbU) {
    constexpr int NTHR = WM * WN * 32;
    constexpr int BK2 = 16;   // uint32 per row per k-tile (32 bf16)
    constexpr int STR = 20;   // padded row stride (conflict-free frag LDS)
    constexpr int S = 3;
    constexpr int WARP_M = BM / WM;
    constexpr int WARP_N = BN / WN;
    constexpr int MT = WARP_M / 16;
    constexpr int NT = WARP_N / 8;

    __shared__ __align__(16) uint32_t As[S][BM][STR];
    __shared__ __align__(16) uint32_t Bs[S][BN][STR];

    const int tid  = threadIdx.x;
    const int lane = tid & 31;
    const int warp = tid >> 5;
    const int gid  = lane >> 2;
    const int tig  = lane & 3;

    const int bm0 = blockIdx.y * BM;
    const int bn0 = blockIdx.x * BN;
    const int wm0 = (warp / WN) * WARP_M;
    const int wn0 = (warp % WN) * WARP_N;

    float acc[MT][NT][4];
    #pragma unroll
    for (int i = 0; i < MT; i++)
        #pragma unroll
        for (int j = 0; j < NT; j++)
            #pragma unroll
            for (int e = 0; e < 4; e++) acc[i][j][e] = 0.f;

    auto load_tile = [&](int buf, int kt) {
        const int k0 = kt * BK2;
        #pragma unroll 2
        for (int s = tid; s < BM * 4; s += NTHR) {
            int r = s >> 2, c = (s & 3) * 4;
            cp16(&As[buf][r][c], A + (size_t)(bm0 + r) * ldaU + k0 + c);
        }
        #pragma unroll 2
        for (int s = tid; s < BN * 4; s += NTHR) {
            int r = s >> 2, c = (s & 3) * 4;
            cp16(&Bs[buf][r][c], W + (size_t)(bn0 + r) * ldwU + k0 + c);
        }
        asm volatile("cp.async.commit_group;");
    };

    const int nkt = K / 32;
    load_tile(0, 0);
    if (nkt > 1) load_tile(1, 1);

    for (int kt = 0; kt < nkt; kt++) {
        const int buf = kt % S;
        if (kt + 1 < nkt) asm volatile("cp.async.wait_group 1;");
        else              asm volatile("cp.async.wait_group 0;");
        __syncthreads();                 // publish tile kt + protect slot reuse
        if (kt + 2 < nkt) load_tile((kt + 2) % S, kt + 2);

        uint32_t af[2][MT][4];
        uint32_t bf[2][NT][2];
        #pragma unroll
        for (int s2 = 0; s2 < 2; s2++) {
            const int k0 = s2 * 8;
            #pragma unroll
            for (int mt = 0; mt < MT; mt++) {
                int r = wm0 + mt * 16;
                af[s2][mt][0] = As[buf][r + gid    ][k0 + tig    ];
                af[s2][mt][1] = As[buf][r + gid + 8][k0 + tig    ];
                af[s2][mt][2] = As[buf][r + gid    ][k0 + tig + 4];
                af[s2][mt][3] = As[buf][r + gid + 8][k0 + tig + 4];
            }
            #pragma unroll
            for (int nt = 0; nt < NT; nt++) {
                int cb = wn0 + nt * 8;
                bf[s2][nt][0] = Bs[buf][cb + gid][k0 + tig    ];
                bf[s2][nt][1] = Bs[buf][cb + gid][k0 + tig + 4];
            }
        }
        #pragma unroll
        for (int s2 = 0; s2 < 2; s2++)
            #pragma unroll
            for (int mt = 0; mt < MT; mt++)
                #pragma unroll
                for (int nt = 0; nt < NT; nt++)
                    mma_bf16(acc[mt][nt], af[s2][mt], bf[s2][nt]);
    }

    // epilogue
    #pragma unroll
    for (int mt = 0; mt < MT; mt++) {
        int r0 = bm0 + wm0 + mt * 16 + gid;
        int r1 = r0 + 8;
        #pragma unroll
        for (int nt = 0; nt < NT; nt++) {
            int cn = bn0 + wn0 + nt * 8 + 2 * tig;
            float v0 = acc[mt][nt][0], v1 = acc[mt][nt][1];
            float v2 = acc[mt][nt][2], v3 = acc[mt][nt][3];
            if (EPI == 1) {
                v0 = softplus_f(v0 + aux[cn]);   v1 = softplus_f(v1 + aux[cn + 1]);
                v2 = softplus_f(v2 + aux[cn]);   v3 = softplus_f(v3 + aux[cn + 1]);
            }
            if (EPI == 2) {
                v0 += aux[(size_t)r0 * ldc + cn];  v1 += aux[(size_t)r0 * ldc + cn + 1];
                v2 += aux[(size_t)r1 * ldc + cn];  v3 += aux[(size_t)r1 * ldc + cn + 1];
            }
            *(float2*)(C + (size_t)r0 * ldc + cn) = make_float2(v0, v1);
            *(float2*)(C + (size_t)r1 * ldc + cn) = make_float2(v2, v3);
            if (EPI == 3 && cn < DTR) {
                Cb[(size_t)r0 * ldcbU + cn / 2] = packbf(v0, v1);
                Cb[(size_t)r1 * ldcbU + cn / 2] = packbf(v2, v3);
            }
        }
    }
}

// ---------------- causal conv(4) + bias + SiLU -> fp32 + bf16 -------------
__global__ void conv_silu_kernel(const float* __restrict__ xz,
                                 const float* __restrict__ cw,
                                 const float* __restrict__ cb,
                                 float* __restrict__ out,
                                 uint32_t* __restrict__ out16) {
    int idx = blockIdx.x * blockDim.x + threadIdx.x;   // pair index
    if (idx >= MTOK * DI / 2) return;
    int dp = idx % (DI / 2);
    int d  = dp * 2;
    int t  = idx / (DI / 2);
    int l  = t % LL;

    const float* up = xz + (size_t)t * (2 * DI) + d;
    float r[2];
    #pragma unroll
    for (int j = 0; j < 2; j++) {
        float w0 = cw[(d + j) * 4 + 0], w1 = cw[(d + j) * 4 + 1];
        float w2 = cw[(d + j) * 4 + 2], w3 = cw[(d + j) * 4 + 3];
        float acc = w3 * up[j];
        if (l >= 1) acc += w2 * up[j - 2 * DI * 1];
        if (l >= 2) acc += w1 * up[j - 2 * DI * 2];
        if (l >= 3) acc += w0 * up[j - 2 * DI * 3];
        acc += cb[d + j];
        r[j] = silu_f(acc);
    }
    ((float2*)out)[idx] = make_float2(r[0], r[1]);
    out16[idx] = packbf(r[0], r[1]);
}

// ---------------- selective scan (unroll-4, prefetch) -> bf16 y ------------
__global__ void scan_kernel(const float* __restrict__ delta,
                            const float* __restrict__ u,
                            const float* __restrict__ xdbl,
                            const float* __restrict__ xz,
                            const float* __restrict__ A_log,
                            const float* __restrict__ Dp,
                            __nv_bfloat16* __restrict__ y16) {
    int gt   = blockIdx.x * blockDim.x + threadIdx.x;
    int w    = gt >> 5;
    int lane = gt & 31;
    if (w >= BB * (DI / 2)) return;

    int b    = w >> 10;
    int pair = w & 1023;
    int dd   = pair * 2 + (lane >> 4);
    int n    = lane & 15;

    float Ad = -expf(A_log[dd * DS + n]);
    float Dd = Dp[dd];
    float h  = 0.f;

    const size_t base_d = (size_t)b * LL * DI + dd;
    const size_t base_x = (size_t)b * LL * XDBL_W;
    const size_t base_z = (size_t)b * LL * (2 * DI) + DI + dd;

    constexpr int U = 4;
    float de[U], uu[U], Bn[U], Cn[U], zv[U];
    #pragma unroll
    for (int j = 0; j < U; j++) {
        de[j] = delta[base_d + (size_t)j * DI];
        uu[j] = u    [base_d + (size_t)j * DI];
        Bn[j] = xdbl [base_x + (size_t)j * XDBL_W + DTR + n];
        Cn[j] = xdbl [base_x + (size_t)j * XDBL_W + DTR + DS + n];
        zv[j] = xz   [base_z + (size_t)j * (2 * DI)];
    }

    for (int t = 0; t < LL; t += U) {
        float cde[U], cuu[U], cBn[U], cCn[U], czv[U];
        #pragma unroll
        for (int j = 0; j < U; j++) {
            cde[j] = de[j]; cuu[j] = uu[j]; cBn[j] = Bn[j];
            cCn[j] = Cn[j]; czv[j] = zv[j];
        }
        if (t + U < LL) {
            const size_t od = base_d + (size_t)(t + U) * DI;
            const size_t ox = base_x + (size_t)(t + U) * XDBL_W;
            const size_t oz = base_z + (size_t)(t + U) * (2 * DI);
            #pragma unroll
            for (int j = 0; j < U; j++) {
                de[j] = delta[od + (size_t)j * DI];
                uu[j] = u    [od + (size_t)j * DI];
                Bn[j] = xdbl [ox + (size_t)j * XDBL_W + DTR + n];
                Cn[j] = xdbl [ox + (size_t)j * XDBL_W + DTR + DS + n];
                zv[j] = xz   [oz + (size_t)j * (2 * DI)];
            }
        }
        float yv[U];
        #pragma unroll
        for (int j = 0; j < U; j++) {
            float dA = __expf(cde[j] * Ad);
            h = fmaf(dA, h, cde[j] * cuu[j] * cBn[j]);
            yv[j] = h * cCn[j];
        }
        #pragma unroll
        for (int o = 8; o > 0; o >>= 1) {
            #pragma unroll
            for (int j = 0; j < U; j++)
                yv[j] += __shfl_xor_sync(0xffffffffu, yv[j], o);
        }
        if (n == 0) {
            #pragma unroll
            for (int j = 0; j < U; j++)
                y16[base_d + (size_t)(t + j) * DI] =
                    __float2bfloat16_rn((yv[j] + cuu[j] * Dd) * silu_f(czv[j]));
        }
    }
}

// ---------------- launch ----------------------------------------------------
extern "C" void kernel_launch(void* const* d_in, const int* in_sizes, int n_in,
                              void* d_out, int out_size) {
    const float* x         = (const float*)d_in[0];
    const float* ln_w      = (const float*)d_in[1];
    const float* ln_b      = (const float*)d_in[2];
    const float* in_proj_w = (const float*)d_in[3];
    const float* conv_w    = (const float*)d_in[4];
    const float* conv_b    = (const float*)d_in[5];
    const float* x_proj_w  = (const float*)d_in[6];
    const float* dt_proj_w = (const float*)d_in[7];
    const float* dt_proj_b = (const float*)d_in[8];
    const float* A_log     = (const float*)d_in[9];
    const float* Dp        = (const float*)d_in[10];
    const float* out_pw    = (const float*)d_in[11];
    float* out = (float*)d_out;

    float *xz, *uconv, *xdbl, *delta;
    uint32_t *xn16, *uconv16, *dt16, *win16, *wx16, *wdt16, *wout16;
    __nv_bfloat16 *y16;
    cudaGetSymbolAddress((void**)&xz,      g_xz);
    cudaGetSymbolAddress((void**)&uconv,   g_uconv);
    cudaGetSymbolAddress((void**)&xdbl,    g_xdbl);
    cudaGetSymbolAddress((void**)&delta,   g_delta);
    cudaGetSymbolAddress((void**)&xn16,    g_xn16);
    cudaGetSymbolAddress((void**)&uconv16, g_uconv16);
    cudaGetSymbolAddress((void**)&dt16,    g_dt16);
    cudaGetSymbolAddress((void**)&y16,     g_y16);
    cudaGetSymbolAddress((void**)&win16,   g_win16);
    cudaGetSymbolAddress((void**)&wx16,    g_wx16);
    cudaGetSymbolAddress((void**)&wdt16,   g_wdt16);
    cudaGetSymbolAddress((void**)&wout16,  g_wout16);

    // 0. weight conversions (bf16, round-to-nearest)
    {
        int n2;
        n2 = 2 * DI * DM / 2;
        f32_to_bf16x2<<<(n2 + 255) / 256, 256>>>(in_proj_w, win16, n2);
        n2 = XDBL_W * DI / 2;
        f32_to_bf16x2<<<(n2 + 255) / 256, 256>>>(x_proj_w, wx16, n2);
        n2 = DI * DTR / 2;
        f32_to_bf16x2<<<(n2 + 255) / 256, 256>>>(dt_proj_w, wdt16, n2);
        n2 = DM * DI / 2;
        f32_to_bf16x2<<<(n2 + 255) / 256, 256>>>(out_pw, wout16, n2);
    }

    // 1. LayerNorm -> xn16 (bf16)
    ln_kernel<<<MTOK, 256>>>(x, ln_w, ln_b, xn16);

    // 2. in_proj: xn16 @ win16^T -> xz fp32 (4096 x 4096)
    gemm_bf16<128, 128, 2, 4, 0><<<dim3((2 * DI) / 128, MTOK / 128), 256>>>(
        xn16, DM / 2, win16, DM / 2, xz, 2 * DI, DM, nullptr, nullptr, 0);

    // 3. conv + SiLU -> uconv fp32 + uconv16
    conv_silu_kernel<<<(MTOK * DI / 2 + 255) / 256, 256>>>(
        xz, conv_w, conv_b, uconv, uconv16);

    // 4. x_proj: uconv16 @ wx16^T -> xdbl fp32 (+ dt16 bf16 for cols < 64)
    gemm_bf16<32, 96, 2, 4, 3><<<dim3(1, MTOK / 32), 256>>>(
        uconv16, DI / 2, wx16, DI / 2, xdbl, XDBL_W, DI, nullptr, dt16, DTR / 2);

    // 5. dt_proj: dt16 @ wdt16^T + bias, softplus -> delta fp32
    gemm_bf16<128, 128, 2, 4, 1><<<dim3(DI / 128, MTOK / 128), 256>>>(
        dt16, DTR / 2, wdt16, DTR / 2, delta, DI, DTR, dt_proj_b, nullptr, 0);

    // 6. selective scan -> y16 (bf16)
    scan_kernel<<<(BB * (DI / 2) * 32) / 128, 128>>>(
        delta, uconv, xdbl, xz, A_log, Dp, y16);

    // 7. out_proj: y16 @ wout16^T + x residual -> out fp32
    gemm_bf16<128, 128, 2, 4, 2><<<dim3(DM / 128, MTOK / 128), 256>>>(
        (const uint32_t*)y16, DI / 2, wout16, DI / 2, out, DM, DI, x, nullptr, 0);
}

// round 6
// speedup vs baseline: 5.7164x; 1.0298x over previous
#include <cuda_runtime.h>
#include <cuda_bf16.h>
#include <math.h>
#include <stdint.h>

// ---------------- problem constants ----------------
#define BB   2
#define LL   2048
#define DM   1024
#define DI   2048
#define DTR  64
#define DS   16
#define MTOK (BB * LL)   // 4096 tokens
#define XDBL_W 96

// ---------------- scratch ----------------
__device__ float    g_xdbl [(size_t)MTOK * XDBL_W];
__device__ float    g_delta[(size_t)MTOK * DI];
__device__ uint32_t g_xn16   [(size_t)MTOK * DM / 2];
__device__ uint32_t g_xz16   [(size_t)MTOK * 2 * DI / 2];   // u|z bf16 packed
__device__ uint32_t g_uconv16[(size_t)MTOK * DI / 2];
__device__ uint32_t g_dt16   [(size_t)MTOK * DTR / 2];
__device__ __nv_bfloat16 g_y16[(size_t)MTOK * DI];
__device__ uint32_t g_win16  [(size_t)2 * DI * DM / 2];
__device__ uint32_t g_wx16   [(size_t)XDBL_W * DI / 2];
__device__ uint32_t g_wdt16  [(size_t)DI * DTR / 2];
__device__ uint32_t g_wout16 [(size_t)DM * DI / 2];

// ---------------- helpers ----------------
__device__ __forceinline__ float softplus_f(float v) {
    return (v > 20.f) ? v : log1pf(__expf(v));
}
__device__ __forceinline__ float silu_f(float v) {
    return v * (1.f / (1.f + __expf(-v)));
}
__device__ __forceinline__ uint32_t packbf(float lo, float hi) {
    __nv_bfloat162 h(__float2bfloat16_rn(lo), __float2bfloat16_rn(hi));
    return *reinterpret_cast<uint32_t*>(&h);
}
__device__ __forceinline__ float2 unpk(uint32_t v) {
    __nv_bfloat162 h = *reinterpret_cast<__nv_bfloat162*>(&v);
    return make_float2(__bfloat162float(h.x), __bfloat162float(h.y));
}
__device__ __forceinline__ void mma_bf16(float* c, const uint32_t* a, const uint32_t* b) {
    asm volatile("mma.sync.aligned.m16n8k16.row.col.f32.bf16.bf16.f32 "
                 "{%0,%1,%2,%3}, {%4,%5,%6,%7}, {%8,%9}, {%0,%1,%2,%3};"
                 : "+f"(c[0]), "+f"(c[1]), "+f"(c[2]), "+f"(c[3])
                 : "r"(a[0]), "r"(a[1]), "r"(a[2]), "r"(a[3]),
                   "r"(b[0]), "r"(b[1]));
}
__device__ __forceinline__ void cp16(void* dst, const void* src) {
    uint32_t d = (uint32_t)__cvta_generic_to_shared(dst);
    asm volatile("cp.async.cg.shared.global [%0], [%1], 16;" :: "r"(d), "l"(src));
}
__device__ __forceinline__ uint32_t smem_u32(const void* p) {
    uint32_t a;
    asm("{ .reg .u64 t; cvta.to.shared.u64 t, %1; cvt.u32.u64 %0, t; }"
        : "=r"(a) : "l"(p));
    return a;
}
__device__ __forceinline__ void ldm_x4(uint32_t* r, uint32_t addr) {
    asm volatile("ldmatrix.sync.aligned.m8n8.x4.shared.b16 {%0,%1,%2,%3}, [%4];"
        : "=r"(r[0]), "=r"(r[1]), "=r"(r[2]), "=r"(r[3]) : "r"(addr));
}

// ---------------- fp32 -> packed bf16 convert ----------------
__global__ void f32_to_bf16x2(const float* __restrict__ src,
                              uint32_t* __restrict__ dst, int n2) {
    int i = blockIdx.x * blockDim.x + threadIdx.x;
    if (i < n2) {
        float2 v = ((const float2*)src)[i];
        dst[i] = packbf(v.x, v.y);
    }
}

// ---------------- LayerNorm -> bf16 packed ----------------
__global__ void ln_kernel(const float* __restrict__ x,
                          const float* __restrict__ w,
                          const float* __restrict__ b,
                          uint32_t* __restrict__ out16) {
    const int row = blockIdx.x;
    const int tid = threadIdx.x;
    const float4* xr = (const float4*)(x + (size_t)row * DM);
    float4 v = xr[tid];

    float s  = v.x + v.y + v.z + v.w;
    float s2 = v.x * v.x + v.y * v.y + v.z * v.z + v.w * v.w;

    __shared__ float shs[8], shs2[8];
    #pragma unroll
    for (int o = 16; o > 0; o >>= 1) {
        s  += __shfl_down_sync(0xffffffffu, s,  o);
        s2 += __shfl_down_sync(0xffffffffu, s2, o);
    }
    if ((tid & 31) == 0) { shs[tid >> 5] = s; shs2[tid >> 5] = s2; }
    __syncthreads();
    float mu = 0.f, m2 = 0.f;
    #pragma unroll
    for (int i = 0; i < 8; i++) { mu += shs[i]; m2 += shs2[i]; }
    mu *= (1.f / DM);
    m2 *= (1.f / DM);
    float inv = rsqrtf(m2 - mu * mu + 1e-5f);

    float4 wv = ((const float4*)w)[tid];
    float4 bv = ((const float4*)b)[tid];
    uint2 p;
    p.x = packbf((v.x - mu) * inv * wv.x + bv.x, (v.y - mu) * inv * wv.y + bv.y);
    p.y = packbf((v.z - mu) * inv * wv.z + bv.z, (v.w - mu) * inv * wv.w + bv.w);
    ((uint2*)(out16 + (size_t)row * (DM / 2)))[tid] = p;
}

// ---------------- bf16 mma.sync GEMM with ldmatrix --------------------------
// C[M,N] = A[M,K] @ W[N,K]^T. Packed bf16 inputs (uint32x2), lda in uint32.
// BK=32 bf16, 3-stage cp.async pipe, one __syncthreads per tile,
// ldmatrix.x4 fragment loads (conflict-free at 20-uint32 row stride).
// EPI: 1 softplus(v+aux[n])->C fp32, 2 v+aux[m*ldc+n]->C fp32,
//      3 C fp32 + bf16 Cb for n<64, 4 bf16-only -> Cb
template<int BM, int BN, int WM, int WN, int EPI>
__global__ __launch_bounds__(WM * WN * 32)
void gemm_lm(const uint32_t* __restrict__ A, int ldaU,
             const uint32_t* __restrict__ W, int ldwU,
             float* __restrict__ C, int ldc, int K,
             const float* __restrict__ aux,
             uint32_t* __restrict__ Cb, int ldcbU) {
    constexpr int NTHR = WM * WN * 32;
    constexpr int BK2 = 16;   // uint32 per row per k-tile (32 bf16)
    constexpr int STR = 20;   // padded row stride in uint32
    constexpr int S = 3;
    constexpr int WARP_M = BM / WM;
    constexpr int WARP_N = BN / WN;
    constexpr int MT = WARP_M / 16;
    constexpr int NT = WARP_N / 8;
    static_assert(NT % 2 == 0, "NT must be even for x4 B loads");

    __shared__ __align__(16) uint32_t As[S][BM][STR];
    __shared__ __align__(16) uint32_t Bs[S][BN][STR];

    const int tid  = threadIdx.x;
    const int lane = tid & 31;
    const int warp = tid >> 5;
    const int gid  = lane >> 2;
    const int tig  = lane & 3;

    const int bm0 = blockIdx.y * BM;
    const int bn0 = blockIdx.x * BN;
    const int wm0 = (warp / WN) * WARP_M;
    const int wn0 = (warp % WN) * WARP_N;

    float acc[MT][NT][4];
    #pragma unroll
    for (int i = 0; i < MT; i++)
        #pragma unroll
        for (int j = 0; j < NT; j++)
            #pragma unroll
            for (int e = 0; e < 4; e++) acc[i][j][e] = 0.f;

    auto load_tile = [&](int buf, int kt) {
        const int k0 = kt * BK2;
        #pragma unroll 2
        for (int s = tid; s < BM * 4; s += NTHR) {
            int r = s >> 2, c = (s & 3) * 4;
            cp16(&As[buf][r][c], A + (size_t)(bm0 + r) * ldaU + k0 + c);
        }
        #pragma unroll 2
        for (int s = tid; s < BN * 4; s += NTHR) {
            int r = s >> 2, c = (s & 3) * 4;
            cp16(&Bs[buf][r][c], W + (size_t)(bn0 + r) * ldwU + k0 + c);
        }
        asm volatile("cp.async.commit_group;");
    };

    const int nkt = K / 32;
    load_tile(0, 0);
    if (nkt > 1) load_tile(1, 1);

    // per-lane ldmatrix address offsets (in uint32 units, within a tile slice)
    const uint32_t a_row = (uint32_t)(lane & 15);
    const uint32_t a_col = (uint32_t)((lane >> 4) << 2);
    const uint32_t b_row = (uint32_t)((lane & 7) + ((lane >> 4) << 3));
    const uint32_t b_col = (uint32_t)(((lane >> 3) & 1) << 2);

    for (int kt = 0; kt < nkt; kt++) {
        const int buf = kt % S;
        if (kt + 1 < nkt) asm volatile("cp.async.wait_group 1;");
        else              asm volatile("cp.async.wait_group 0;");
        __syncthreads();
        if (kt + 2 < nkt) load_tile((kt + 2) % S, kt + 2);

        const uint32_t abase = smem_u32(&As[buf][0][0]);
        const uint32_t bbase = smem_u32(&Bs[buf][0][0]);

        #pragma unroll
        for (int ks = 0; ks < 2; ks++) {
            uint32_t af[MT][4];
            uint32_t bf[NT][2];
            #pragma unroll
            for (int mt = 0; mt < MT; mt++) {
                uint32_t r = (uint32_t)(wm0 + mt * 16) + a_row;
                ldm_x4(af[mt], abase + (r * STR + ks * 8 + a_col) * 4);
            }
            #pragma unroll
            for (int ip = 0; ip < NT / 2; ip++) {
                uint32_t r = (uint32_t)(wn0 + ip * 16) + b_row;
                uint32_t q[4];
                ldm_x4(q, bbase + (r * STR + ks * 8 + b_col) * 4);
                bf[2 * ip][0]     = q[0]; bf[2 * ip][1]     = q[1];
                bf[2 * ip + 1][0] = q[2]; bf[2 * ip + 1][1] = q[3];
            }
            #pragma unroll
            for (int mt = 0; mt < MT; mt++)
                #pragma unroll
                for (int nt = 0; nt < NT; nt++)
                    mma_bf16(acc[mt][nt], af[mt], bf[nt]);
        }
    }

    // epilogue
    #pragma unroll
    for (int mt = 0; mt < MT; mt++) {
        int r0 = bm0 + wm0 + mt * 16 + gid;
        int r1 = r0 + 8;
        #pragma unroll
        for (int nt = 0; nt < NT; nt++) {
            int cn = bn0 + wn0 + nt * 8 + 2 * tig;
            float v0 = acc[mt][nt][0], v1 = acc[mt][nt][1];
            float v2 = acc[mt][nt][2], v3 = acc[mt][nt][3];
            if (EPI == 4) {
                Cb[(size_t)r0 * ldcbU + cn / 2] = packbf(v0, v1);
                Cb[(size_t)r1 * ldcbU + cn / 2] = packbf(v2, v3);
                continue;
            }
            if (EPI == 1) {
                v0 = softplus_f(v0 + aux[cn]);   v1 = softplus_f(v1 + aux[cn + 1]);
                v2 = softplus_f(v2 + aux[cn]);   v3 = softplus_f(v3 + aux[cn + 1]);
            }
            if (EPI == 2) {
                v0 += aux[(size_t)r0 * ldc + cn];  v1 += aux[(size_t)r0 * ldc + cn + 1];
                v2 += aux[(size_t)r1 * ldc + cn];  v3 += aux[(size_t)r1 * ldc + cn + 1];
            }
            *(float2*)(C + (size_t)r0 * ldc + cn) = make_float2(v0, v1);
            *(float2*)(C + (size_t)r1 * ldc + cn) = make_float2(v2, v3);
            if (EPI == 3 && cn < DTR) {
                Cb[(size_t)r0 * ldcbU + cn / 2] = packbf(v0, v1);
                Cb[(size_t)r1 * ldcbU + cn / 2] = packbf(v2, v3);
            }
        }
    }
}

// ---------------- causal conv(4) + bias + SiLU (bf16 in/out) ---------------
__global__ void conv_silu_kernel(const uint32_t* __restrict__ xz16,
                                 const float* __restrict__ cw,
                                 const float* __restrict__ cb,
                                 uint32_t* __restrict__ out16) {
    int idx = blockIdx.x * blockDim.x + threadIdx.x;   // pair index
    if (idx >= MTOK * DI / 2) return;
    int dp = idx % (DI / 2);
    int d  = dp * 2;
    int t  = idx / (DI / 2);
    int l  = t % LL;

    const uint32_t* up = xz16 + (size_t)t * (2 * DI / 2) + dp;
    float2 c0 = unpk(up[0]);
    float2 c1 = (l >= 1) ? unpk(up[-(2 * DI / 2) * 1]) : make_float2(0.f, 0.f);
    float2 c2 = (l >= 2) ? unpk(up[-(2 * DI / 2) * 2]) : make_float2(0.f, 0.f);
    float2 c3 = (l >= 3) ? unpk(up[-(2 * DI / 2) * 3]) : make_float2(0.f, 0.f);

    float4 wA = *(const float4*)(cw + (size_t)d * 4);       // w[d][0..3]
    float4 wB = *(const float4*)(cw + (size_t)(d + 1) * 4); // w[d+1][0..3]
    float r0 = silu_f(wA.w * c0.x + wA.z * c1.x + wA.y * c2.x + wA.x * c3.x + cb[d]);
    float r1 = silu_f(wB.w * c0.y + wB.z * c1.y + wB.y * c2.y + wB.x * c3.y + cb[d + 1]);
    out16[idx] = packbf(r0, r1);
}

// ---------------- selective scan (unroll-4, prefetch, bf16 u/z) ------------
__global__ void scan_kernel(const float* __restrict__ delta,
                            const uint32_t* __restrict__ u16,
                            const float* __restrict__ xdbl,
                            const uint32_t* __restrict__ xz16,
                            const float* __restrict__ A_log,
                            const float* __restrict__ Dp,
                            __nv_bfloat16* __restrict__ y16) {
    int gt   = blockIdx.x * blockDim.x + threadIdx.x;
    int w    = gt >> 5;
    int lane = gt & 31;
    if (w >= BB * (DI / 2)) return;

    int b    = w >> 10;
    int pair = w & 1023;
    int hi   = (lane >> 4);              // which channel of the pair
    int dd   = pair * 2 + hi;
    int n    = lane & 15;

    float Ad = -expf(A_log[dd * DS + n]);
    float Dd = Dp[dd];
    float h  = 0.f;

    const size_t base_d = (size_t)b * LL * DI + dd;           // fp32 delta / y16
    const size_t base_u = (size_t)b * LL * (DI / 2) + pair;   // bf16 pairs
    const size_t base_x = (size_t)b * LL * XDBL_W;
    const size_t base_z = (size_t)b * LL * (2 * DI / 2) + DI / 2 + pair;

    constexpr int U = 4;
    float de[U], Bn[U], Cn[U];
    uint32_t uup[U], zzp[U];
    #pragma unroll
    for (int j = 0; j < U; j++) {
        de[j]  = delta[base_d + (size_t)j * DI];
        uup[j] = u16 [base_u + (size_t)j * (DI / 2)];
        Bn[j]  = xdbl[base_x + (size_t)j * XDBL_W + DTR + n];
        Cn[j]  = xdbl[base_x + (size_t)j * XDBL_W + DTR + DS + n];
        zzp[j] = xz16[base_z + (size_t)j * (2 * DI / 2)];
    }

    for (int t = 0; t < LL; t += U) {
        float cde[U], cBn[U], cCn[U], cuu[U], czv[U];
        #pragma unroll
        for (int j = 0; j < U; j++) {
            cde[j] = de[j]; cBn[j] = Bn[j]; cCn[j] = Cn[j];
            float2 uv = unpk(uup[j]);
            float2 zv2 = unpk(zzp[j]);
            cuu[j] = hi ? uv.y : uv.x;
            czv[j] = hi ? zv2.y : zv2.x;
        }
        if (t + U < LL) {
            const size_t od = base_d + (size_t)(t + U) * DI;
            const size_t ou = base_u + (size_t)(t + U) * (DI / 2);
            const size_t ox = base_x + (size_t)(t + U) * XDBL_W;
            const size_t oz = base_z + (size_t)(t + U) * (2 * DI / 2);
            #pragma unroll
            for (int j = 0; j < U; j++) {
                de[j]  = delta[od + (size_t)j * DI];
                uup[j] = u16 [ou + (size_t)j * (DI / 2)];
                Bn[j]  = xdbl[ox + (size_t)j * XDBL_W + DTR + n];
                Cn[j]  = xdbl[ox + (size_t)j * XDBL_W + DTR + DS + n];
                zzp[j] = xz16[oz + (size_t)j * (2 * DI / 2)];
            }
        }
        float yv[U];
        #pragma unroll
        for (int j = 0; j < U; j++) {
            float dA = __expf(cde[j] * Ad);
            h = fmaf(dA, h, cde[j] * cuu[j] * cBn[j]);
            yv[j] = h * cCn[j];
        }
        #pragma unroll
        for (int o = 8; o > 0; o >>= 1) {
            #pragma unroll
            for (int j = 0; j < U; j++)
                yv[j] += __shfl_xor_sync(0xffffffffu, yv[j], o);
        }
        if (n == 0) {
            #pragma unroll
            for (int j = 0; j < U; j++)
                y16[base_d + (size_t)(t + j) * DI] =
                    __float2bfloat16_rn((yv[j] + cuu[j] * Dd) * silu_f(czv[j]));
        }
    }
}

// ---------------- launch ----------------------------------------------------
extern "C" void kernel_launch(void* const* d_in, const int* in_sizes, int n_in,
                              void* d_out, int out_size) {
    const float* x         = (const float*)d_in[0];
    const float* ln_w      = (const float*)d_in[1];
    const float* ln_b      = (const float*)d_in[2];
    const float* in_proj_w = (const float*)d_in[3];
    const float* conv_w    = (const float*)d_in[4];
    const float* conv_b    = (const float*)d_in[5];
    const float* x_proj_w  = (const float*)d_in[6];
    const float* dt_proj_w = (const float*)d_in[7];
    const float* dt_proj_b = (const float*)d_in[8];
    const float* A_log     = (const float*)d_in[9];
    const float* Dp        = (const float*)d_in[10];
    const float* out_pw    = (const float*)d_in[11];
    float* out = (float*)d_out;

    float *xdbl, *delta;
    uint32_t *xn16, *xz16, *uconv16, *dt16, *win16, *wx16, *wdt16, *wout16;
    __nv_bfloat16* y16;
    cudaGetSymbolAddress((void**)&xdbl,    g_xdbl);
    cudaGetSymbolAddress((void**)&delta,   g_delta);
    cudaGetSymbolAddress((void**)&xn16,    g_xn16);
    cudaGetSymbolAddress((void**)&xz16,    g_xz16);
    cudaGetSymbolAddress((void**)&uconv16, g_uconv16);
    cudaGetSymbolAddress((void**)&dt16,    g_dt16);
    cudaGetSymbolAddress((void**)&y16,     g_y16);
    cudaGetSymbolAddress((void**)&win16,   g_win16);
    cudaGetSymbolAddress((void**)&wx16,    g_wx16);
    cudaGetSymbolAddress((void**)&wdt16,   g_wdt16);
    cudaGetSymbolAddress((void**)&wout16,  g_wout16);

    // 0. weight conversions
    {
        int n2;
        n2 = 2 * DI * DM / 2;
        f32_to_bf16x2<<<(n2 + 255) / 256, 256>>>(in_proj_w, win16, n2);
        n2 = XDBL_W * DI / 2;
        f32_to_bf16x2<<<(n2 + 255) / 256, 256>>>(x_proj_w, wx16, n2);
        n2 = DI * DTR / 2;
        f32_to_bf16x2<<<(n2 + 255) / 256, 256>>>(dt_proj_w, wdt16, n2);
        n2 = DM * DI / 2;
        f32_to_bf16x2<<<(n2 + 255) / 256, 256>>>(out_pw, wout16, n2);
    }

    // 1. LayerNorm -> xn16
    ln_kernel<<<MTOK, 256>>>(x, ln_w, ln_b, xn16);

    // 2. in_proj: xn16 @ win16^T -> xz16 (bf16 packed)
    gemm_lm<128, 128, 2, 4, 4><<<dim3((2 * DI) / 128, MTOK / 128), 256>>>(
        xn16, DM / 2, win16, DM / 2, nullptr, 0, DM, nullptr, xz16, 2 * DI / 2);

    // 3. conv + SiLU: xz16(u) -> uconv16
    conv_silu_kernel<<<(MTOK * DI / 2 + 255) / 256, 256>>>(
        xz16, conv_w, conv_b, uconv16);

    // 4. x_proj: uconv16 @ wx16^T -> xdbl fp32 (+ dt16 bf16 for n<64)
    gemm_lm<32, 96, 2, 3, 3><<<dim3(1, MTOK / 32), 192>>>(
        uconv16, DI / 2, wx16, DI / 2, xdbl, XDBL_W, DI, nullptr, dt16, DTR / 2);

    // 5. dt_proj: dt16 @ wdt16^T +bias, softplus -> delta fp32
    gemm_lm<128, 128, 2, 4, 1><<<dim3(DI / 128, MTOK / 128), 256>>>(
        dt16, DTR / 2, wdt16, DTR / 2, delta, DI, DTR, dt_proj_b, nullptr, 0);

    // 6. selective scan -> y16
    scan_kernel<<<(BB * (DI / 2) * 32) / 128, 128>>>(
        delta, uconv16, xdbl, xz16, A_log, Dp, y16);

    // 7. out_proj: y16 @ wout16^T + x residual -> out fp32
    gemm_lm<128, 128, 2, 4, 2><<<dim3(DM / 128, MTOK / 128), 256>>>(
        (const uint32_t*)y16, DI / 2, wout16, DI / 2, out, DM, DI, x, nullptr, 0);
}

// round 7
// speedup vs baseline: 6.2847x; 1.0994x over previous
#include <cuda_runtime.h>
#include <cuda_bf16.h>
#include <math.h>
#include <stdint.h>

// ---------------- problem constants ----------------
#define BB   2
#define LL   2048
#define DM   1024
#define DI   2048
#define DTR  64
#define DS   16
#define MTOK (BB * LL)   // 4096 tokens
#define XDBL_W 96
#define GCH  16          // scan chunks
#define CHLEN (LL / GCH) // 128

// ---------------- scratch ----------------
__device__ float    g_xdbl [(size_t)MTOK * XDBL_W];
__device__ float    g_delta[(size_t)MTOK * DI];
__device__ uint32_t g_xn16   [(size_t)MTOK * DM / 2];
__device__ uint32_t g_xz16   [(size_t)MTOK * 2 * DI / 2];   // u|z bf16 packed
__device__ uint32_t g_uconv16[(size_t)MTOK * DI / 2];
__device__ uint32_t g_dt16   [(size_t)MTOK * DTR / 2];
__device__ __nv_bfloat16 g_y16[(size_t)MTOK * DI];
__device__ uint32_t g_win16  [(size_t)2 * DI * DM / 2];
__device__ uint32_t g_wx16   [(size_t)XDBL_W * DI / 2];
__device__ uint32_t g_wdt16  [(size_t)DI * DTR / 2];
__device__ uint32_t g_wout16 [(size_t)DM * DI / 2];
// scan carries: [(b*DI+dd)*DS+n][GCH]
__device__ float g_Ac[(size_t)BB * DI * DS * GCH];
__device__ float g_Hc[(size_t)BB * DI * DS * GCH];
__device__ float g_Ci[(size_t)BB * DI * DS * GCH];

// ---------------- helpers ----------------
__device__ __forceinline__ float softplus_f(float v) {
    return (v > 20.f) ? v : log1pf(__expf(v));
}
__device__ __forceinline__ float silu_f(float v) {
    return v * (1.f / (1.f + __expf(-v)));
}
__device__ __forceinline__ uint32_t packbf(float lo, float hi) {
    __nv_bfloat162 h(__float2bfloat16_rn(lo), __float2bfloat16_rn(hi));
    return *reinterpret_cast<uint32_t*>(&h);
}
__device__ __forceinline__ float2 unpk(uint32_t v) {
    __nv_bfloat162 h = *reinterpret_cast<__nv_bfloat162*>(&v);
    return make_float2(__bfloat162float(h.x), __bfloat162float(h.y));
}
__device__ __forceinline__ void mma_bf16(float* c, const uint32_t* a, const uint32_t* b) {
    asm volatile("mma.sync.aligned.m16n8k16.row.col.f32.bf16.bf16.f32 "
                 "{%0,%1,%2,%3}, {%4,%5,%6,%7}, {%8,%9}, {%0,%1,%2,%3};"
                 : "+f"(c[0]), "+f"(c[1]), "+f"(c[2]), "+f"(c[3])
                 : "r"(a[0]), "r"(a[1]), "r"(a[2]), "r"(a[3]),
                   "r"(b[0]), "r"(b[1]));
}
__device__ __forceinline__ void cp16(void* dst, const void* src) {
    uint32_t d = (uint32_t)__cvta_generic_to_shared(dst);
    asm volatile("cp.async.cg.shared.global [%0], [%1], 16;" :: "r"(d), "l"(src));
}
__device__ __forceinline__ uint32_t smem_u32(const void* p) {
    uint32_t a;
    asm("{ .reg .u64 t; cvta.to.shared.u64 t, %1; cvt.u32.u64 %0, t; }"
        : "=r"(a) : "l"(p));
    return a;
}
__device__ __forceinline__ void ldm_x4(uint32_t* r, uint32_t addr) {
    asm volatile("ldmatrix.sync.aligned.m8n8.x4.shared.b16 {%0,%1,%2,%3}, [%4];"
        : "=r"(r[0]), "=r"(r[1]), "=r"(r[2]), "=r"(r[3]) : "r"(addr));
}

// ---------------- one fused weight conversion ----------------
#define CN1 (2 * DI * DM / 2)
#define CN2 (XDBL_W * DI / 2)
#define CN3 (DI * DTR / 2)
#define CN4 (DM * DI / 2)
__global__ void convert_all(const float* __restrict__ w1, const float* __restrict__ w2,
                            const float* __restrict__ w3, const float* __restrict__ w4,
                            uint32_t* __restrict__ d1, uint32_t* __restrict__ d2,
                            uint32_t* __restrict__ d3, uint32_t* __restrict__ d4) {
    int i = blockIdx.x * blockDim.x + threadIdx.x;
    const float2* s; uint32_t* d; int j;
    if (i < CN1)                      { s = (const float2*)w1; d = d1; j = i; }
    else if (i < CN1 + CN2)           { s = (const float2*)w2; d = d2; j = i - CN1; }
    else if (i < CN1 + CN2 + CN3)     { s = (const float2*)w3; d = d3; j = i - CN1 - CN2; }
    else if (i < CN1 + CN2 + CN3 + CN4){ s = (const float2*)w4; d = d4; j = i - CN1 - CN2 - CN3; }
    else return;
    float2 v = s[j];
    d[j] = packbf(v.x, v.y);
}

// ---------------- LayerNorm -> bf16 packed ----------------
__global__ void ln_kernel(const float* __restrict__ x,
                          const float* __restrict__ w,
                          const float* __restrict__ b,
                          uint32_t* __restrict__ out16) {
    const int row = blockIdx.x;
    const int tid = threadIdx.x;
    const float4* xr = (const float4*)(x + (size_t)row * DM);
    float4 v = xr[tid];

    float s  = v.x + v.y + v.z + v.w;
    float s2 = v.x * v.x + v.y * v.y + v.z * v.z + v.w * v.w;

    __shared__ float shs[8], shs2[8];
    #pragma unroll
    for (int o = 16; o > 0; o >>= 1) {
        s  += __shfl_down_sync(0xffffffffu, s,  o);
        s2 += __shfl_down_sync(0xffffffffu, s2, o);
    }
    if ((tid & 31) == 0) { shs[tid >> 5] = s; shs2[tid >> 5] = s2; }
    __syncthreads();
    float mu = 0.f, m2 = 0.f;
    #pragma unroll
    for (int i = 0; i < 8; i++) { mu += shs[i]; m2 += shs2[i]; }
    mu *= (1.f / DM);
    m2 *= (1.f / DM);
    float inv = rsqrtf(m2 - mu * mu + 1e-5f);

    float4 wv = ((const float4*)w)[tid];
    float4 bv = ((const float4*)b)[tid];
    uint2 p;
    p.x = packbf((v.x - mu) * inv * wv.x + bv.x, (v.y - mu) * inv * wv.y + bv.y);
    p.y = packbf((v.z - mu) * inv * wv.z + bv.z, (v.w - mu) * inv * wv.w + bv.w);
    ((uint2*)(out16 + (size_t)row * (DM / 2)))[tid] = p;
}

// ---------------- bf16 mma.sync GEMM with ldmatrix --------------------------
template<int BM, int BN, int WM, int WN, int EPI>
__global__ __launch_bounds__(WM * WN * 32)
void gemm_lm(const uint32_t* __restrict__ A, int ldaU,
             const uint32_t* __restrict__ W, int ldwU,
             float* __restrict__ C, int ldc, int K,
             const float* __restrict__ aux,
             uint32_t* __restrict__ Cb, int ldcbU) {
    constexpr int NTHR = WM * WN * 32;
    constexpr int BK2 = 16;
    constexpr int STR = 20;
    constexpr int S = 3;
    constexpr int WARP_M = BM / WM;
    constexpr int WARP_N = BN / WN;
    constexpr int MT = WARP_M / 16;
    constexpr int NT = WARP_N / 8;
    static_assert(NT % 2 == 0, "NT must be even for x4 B loads");

    __shared__ __align__(16) uint32_t As[S][BM][STR];
    __shared__ __align__(16) uint32_t Bs[S][BN][STR];

    const int tid  = threadIdx.x;
    const int lane = tid & 31;
    const int warp = tid >> 5;
    const int gid  = lane >> 2;
    const int tig  = lane & 3;

    const int bm0 = blockIdx.y * BM;
    const int bn0 = blockIdx.x * BN;
    const int wm0 = (warp / WN) * WARP_M;
    const int wn0 = (warp % WN) * WARP_N;

    float acc[MT][NT][4];
    #pragma unroll
    for (int i = 0; i < MT; i++)
        #pragma unroll
        for (int j = 0; j < NT; j++)
            #pragma unroll
            for (int e = 0; e < 4; e++) acc[i][j][e] = 0.f;

    auto load_tile = [&](int buf, int kt) {
        const int k0 = kt * BK2;
        #pragma unroll 2
        for (int s = tid; s < BM * 4; s += NTHR) {
            int r = s >> 2, c = (s & 3) * 4;
            cp16(&As[buf][r][c], A + (size_t)(bm0 + r) * ldaU + k0 + c);
        }
        #pragma unroll 2
        for (int s = tid; s < BN * 4; s += NTHR) {
            int r = s >> 2, c = (s & 3) * 4;
            cp16(&Bs[buf][r][c], W + (size_t)(bn0 + r) * ldwU + k0 + c);
        }
        asm volatile("cp.async.commit_group;");
    };

    const int nkt = K / 32;
    load_tile(0, 0);
    if (nkt > 1) load_tile(1, 1);

    const uint32_t a_row = (uint32_t)(lane & 15);
    const uint32_t a_col = (uint32_t)((lane >> 4) << 2);
    const uint32_t b_row = (uint32_t)((lane & 7) + ((lane >> 4) << 3));
    const uint32_t b_col = (uint32_t)(((lane >> 3) & 1) << 2);

    for (int kt = 0; kt < nkt; kt++) {
        const int buf = kt % S;
        if (kt + 1 < nkt) asm volatile("cp.async.wait_group 1;");
        else              asm volatile("cp.async.wait_group 0;");
        __syncthreads();
        if (kt + 2 < nkt) load_tile((kt + 2) % S, kt + 2);

        const uint32_t abase = smem_u32(&As[buf][0][0]);
        const uint32_t bbase = smem_u32(&Bs[buf][0][0]);

        #pragma unroll
        for (int ks = 0; ks < 2; ks++) {
            uint32_t af[MT][4];
            uint32_t bf[NT][2];
            #pragma unroll
            for (int mt = 0; mt < MT; mt++) {
                uint32_t r = (uint32_t)(wm0 + mt * 16) + a_row;
                ldm_x4(af[mt], abase + (r * STR + ks * 8 + a_col) * 4);
            }
            #pragma unroll
            for (int ip = 0; ip < NT / 2; ip++) {
                uint32_t r = (uint32_t)(wn0 + ip * 16) + b_row;
                uint32_t q[4];
                ldm_x4(q, bbase + (r * STR + ks * 8 + b_col) * 4);
                bf[2 * ip][0]     = q[0]; bf[2 * ip][1]     = q[1];
                bf[2 * ip + 1][0] = q[2]; bf[2 * ip + 1][1] = q[3];
            }
            #pragma unroll
            for (int mt = 0; mt < MT; mt++)
                #pragma unroll
                for (int nt = 0; nt < NT; nt++)
                    mma_bf16(acc[mt][nt], af[mt], bf[nt]);
        }
    }

    #pragma unroll
    for (int mt = 0; mt < MT; mt++) {
        int r0 = bm0 + wm0 + mt * 16 + gid;
        int r1 = r0 + 8;
        #pragma unroll
        for (int nt = 0; nt < NT; nt++) {
            int cn = bn0 + wn0 + nt * 8 + 2 * tig;
            float v0 = acc[mt][nt][0], v1 = acc[mt][nt][1];
            float v2 = acc[mt][nt][2], v3 = acc[mt][nt][3];
            if (EPI == 4) {
                Cb[(size_t)r0 * ldcbU + cn / 2] = packbf(v0, v1);
                Cb[(size_t)r1 * ldcbU + cn / 2] = packbf(v2, v3);
                continue;
            }
            if (EPI == 1) {
                v0 = softplus_f(v0 + aux[cn]);   v1 = softplus_f(v1 + aux[cn + 1]);
                v2 = softplus_f(v2 + aux[cn]);   v3 = softplus_f(v3 + aux[cn + 1]);
            }
            if (EPI == 2) {
                v0 += aux[(size_t)r0 * ldc + cn];  v1 += aux[(size_t)r0 * ldc + cn + 1];
                v2 += aux[(size_t)r1 * ldc + cn];  v3 += aux[(size_t)r1 * ldc + cn + 1];
            }
            *(float2*)(C + (size_t)r0 * ldc + cn) = make_float2(v0, v1);
            *(float2*)(C + (size_t)r1 * ldc + cn) = make_float2(v2, v3);
            if (EPI == 3 && cn < DTR) {
                Cb[(size_t)r0 * ldcbU + cn / 2] = packbf(v0, v1);
                Cb[(size_t)r1 * ldcbU + cn / 2] = packbf(v2, v3);
            }
        }
    }
}

// ---------------- causal conv(4) + bias + SiLU (bf16 in/out) ---------------
__global__ void conv_silu_kernel(const uint32_t* __restrict__ xz16,
                                 const float* __restrict__ cw,
                                 const float* __restrict__ cb,
                                 uint32_t* __restrict__ out16) {
    int idx = blockIdx.x * blockDim.x + threadIdx.x;
    if (idx >= MTOK * DI / 2) return;
    int dp = idx % (DI / 2);
    int d  = dp * 2;
    int t  = idx / (DI / 2);
    int l  = t % LL;

    const uint32_t* up = xz16 + (size_t)t * (2 * DI / 2) + dp;
    float2 c0 = unpk(up[0]);
    float2 c1 = (l >= 1) ? unpk(up[-(2 * DI / 2) * 1]) : make_float2(0.f, 0.f);
    float2 c2 = (l >= 2) ? unpk(up[-(2 * DI / 2) * 2]) : make_float2(0.f, 0.f);
    float2 c3 = (l >= 3) ? unpk(up[-(2 * DI / 2) * 3]) : make_float2(0.f, 0.f);

    float4 wA = *(const float4*)(cw + (size_t)d * 4);
    float4 wB = *(const float4*)(cw + (size_t)(d + 1) * 4);
    float r0 = silu_f(wA.w * c0.x + wA.z * c1.x + wA.y * c2.x + wA.x * c3.x + cb[d]);
    float r1 = silu_f(wB.w * c0.y + wB.z * c1.y + wB.y * c2.y + wB.x * c3.y + cb[d + 1]);
    out16[idx] = packbf(r0, r1);
}

// ---------------- chunked selective scan ------------------------------------
// warp decode shared by pass1/pass3: warp w -> (b, pair, g); lane -> (hi, n)
// pass1: chunk-local recurrence from h=0; writes A_chunk (prod of dA) and
//        H_chunk (local h out) at [(b*DI+dd)*DS+n]*GCH + g.
__global__ void scan_p1(const float* __restrict__ delta,
                        const uint32_t* __restrict__ u16,
                        const float* __restrict__ xdbl,
                        const float* __restrict__ A_log,
                        float* __restrict__ gAc, float* __restrict__ gHc) {
    int gt   = blockIdx.x * blockDim.x + threadIdx.x;
    int w    = gt >> 5;
    int lane = gt & 31;
    if (w >= BB * (DI / 2) * GCH) return;

    int pair = w & 1023;
    int b    = (w >> 10) & 1;
    int g    = w >> 11;
    int hi   = lane >> 4;
    int dd   = pair * 2 + hi;
    int n    = lane & 15;
    int t0   = g * CHLEN;

    float Ad = -expf(A_log[dd * DS + n]);
    float h = 0.f, ap = 1.f;

    const size_t base_d = (size_t)(b * LL + t0) * DI + dd;
    const size_t base_u = (size_t)(b * LL + t0) * (DI / 2) + pair;
    const size_t base_x = (size_t)(b * LL + t0) * XDBL_W;

    constexpr int U = 4;
    float de[U], Bn[U];
    uint32_t uup[U];
    #pragma unroll
    for (int j = 0; j < U; j++) {
        de[j]  = delta[base_d + (size_t)j * DI];
        uup[j] = u16 [base_u + (size_t)j * (DI / 2)];
        Bn[j]  = xdbl[base_x + (size_t)j * XDBL_W + DTR + n];
    }
    for (int t = 0; t < CHLEN; t += U) {
        float cde[U], cBn[U], cuu[U];
        #pragma unroll
        for (int j = 0; j < U; j++) {
            cde[j] = de[j]; cBn[j] = Bn[j];
            float2 uv = unpk(uup[j]);
            cuu[j] = hi ? uv.y : uv.x;
        }
        if (t + U < CHLEN) {
            const size_t od = base_d + (size_t)(t + U) * DI;
            const size_t ou = base_u + (size_t)(t + U) * (DI / 2);
            const size_t ox = base_x + (size_t)(t + U) * XDBL_W;
            #pragma unroll
            for (int j = 0; j < U; j++) {
                de[j]  = delta[od + (size_t)j * DI];
                uup[j] = u16 [ou + (size_t)j * (DI / 2)];
                Bn[j]  = xdbl[ox + (size_t)j * XDBL_W + DTR + n];
            }
        }
        #pragma unroll
        for (int j = 0; j < U; j++) {
            float dA = __expf(cde[j] * Ad);
            h = fmaf(dA, h, cde[j] * cuu[j] * cBn[j]);
            ap *= dA;
        }
    }
    size_t idx = ((size_t)(b * DI + dd) * DS + n) * GCH + g;
    gAc[idx] = ap;
    gHc[idx] = h;
}

// pass2: sequential carry over G chunks per (b,dd,n); writes carry-IN per chunk
__global__ void scan_p2(const float* __restrict__ gAc,
                        const float* __restrict__ gHc,
                        float* __restrict__ gCi) {
    int i = blockIdx.x * blockDim.x + threadIdx.x;
    if (i >= BB * DI * DS) return;
    size_t base = (size_t)i * GCH;
    float c = 0.f;
    #pragma unroll
    for (int g = 0; g < GCH; g++) {
        gCi[base + g] = c;
        c = fmaf(gAc[base + g], c, gHc[base + g]);
    }
}

// pass3: recompute in-chunk recurrence from true carry-in; emit gated y (bf16)
__global__ void scan_p3(const float* __restrict__ delta,
                        const uint32_t* __restrict__ u16,
                        const float* __restrict__ xdbl,
                        const uint32_t* __restrict__ xz16,
                        const float* __restrict__ A_log,
                        const float* __restrict__ Dp,
                        const float* __restrict__ gCi,
                        __nv_bfloat16* __restrict__ y16) {
    int gt   = blockIdx.x * blockDim.x + threadIdx.x;
    int w    = gt >> 5;
    int lane = gt & 31;
    if (w >= BB * (DI / 2) * GCH) return;

    int pair = w & 1023;
    int b    = (w >> 10) & 1;
    int g    = w >> 11;
    int hi   = lane >> 4;
    int dd   = pair * 2 + hi;
    int n    = lane & 15;
    int t0   = g * CHLEN;

    float Ad = -expf(A_log[dd * DS + n]);
    float Dd = Dp[dd];
    float h  = gCi[((size_t)(b * DI + dd) * DS + n) * GCH + g];

    const size_t base_d = (size_t)(b * LL + t0) * DI + dd;
    const size_t base_u = (size_t)(b * LL + t0) * (DI / 2) + pair;
    const size_t base_x = (size_t)(b * LL + t0) * XDBL_W;
    const size_t base_z = (size_t)(b * LL + t0) * (2 * DI / 2) + DI / 2 + pair;

    constexpr int U = 4;
    float de[U], Bn[U], Cn[U];
    uint32_t uup[U], zzp[U];
    #pragma unroll
    for (int j = 0; j < U; j++) {
        de[j]  = delta[base_d + (size_t)j * DI];
        uup[j] = u16 [base_u + (size_t)j * (DI / 2)];
        Bn[j]  = xdbl[base_x + (size_t)j * XDBL_W + DTR + n];
        Cn[j]  = xdbl[base_x + (size_t)j * XDBL_W + DTR + DS + n];
        zzp[j] = xz16[base_z + (size_t)j * (2 * DI / 2)];
    }
    for (int t = 0; t < CHLEN; t += U) {
        float cde[U], cBn[U], cCn[U], cuu[U], czv[U];
        #pragma unroll
        for (int j = 0; j < U; j++) {
            cde[j] = de[j]; cBn[j] = Bn[j]; cCn[j] = Cn[j];
            float2 uv = unpk(uup[j]);
            float2 zv2 = unpk(zzp[j]);
            cuu[j] = hi ? uv.y : uv.x;
            czv[j] = hi ? zv2.y : zv2.x;
        }
        if (t + U < CHLEN) {
            const size_t od = base_d + (size_t)(t + U) * DI;
            const size_t ou = base_u + (size_t)(t + U) * (DI / 2);
            const size_t ox = base_x + (size_t)(t + U) * XDBL_W;
            const size_t oz = base_z + (size_t)(t + U) * (2 * DI / 2);
            #pragma unroll
            for (int j = 0; j < U; j++) {
                de[j]  = delta[od + (size_t)j * DI];
                uup[j] = u16 [ou + (size_t)j * (DI / 2)];
                Bn[j]  = xdbl[ox + (size_t)j * XDBL_W + DTR + n];
                Cn[j]  = xdbl[ox + (size_t)j * XDBL_W + DTR + DS + n];
                zzp[j] = xz16[oz + (size_t)j * (2 * DI / 2)];
            }
        }
        float yv[U];
        #pragma unroll
        for (int j = 0; j < U; j++) {
            float dA = __expf(cde[j] * Ad);
            h = fmaf(dA, h, cde[j] * cuu[j] * cBn[j]);
            yv[j] = h * cCn[j];
        }
        #pragma unroll
        for (int o = 8; o > 0; o >>= 1) {
            #pragma unroll
            for (int j = 0; j < U; j++)
                yv[j] += __shfl_xor_sync(0xffffffffu, yv[j], o);
        }
        if (n == 0) {
            #pragma unroll
            for (int j = 0; j < U; j++)
                y16[base_d + (size_t)(t + j) * DI] =
                    __float2bfloat16_rn((yv[j] + cuu[j] * Dd) * silu_f(czv[j]));
        }
    }
}

// ---------------- launch ----------------------------------------------------
extern "C" void kernel_launch(void* const* d_in, const int* in_sizes, int n_in,
                              void* d_out, int out_size) {
    const float* x         = (const float*)d_in[0];
    const float* ln_w      = (const float*)d_in[1];
    const float* ln_b      = (const float*)d_in[2];
    const float* in_proj_w = (const float*)d_in[3];
    const float* conv_w    = (const float*)d_in[4];
    const float* conv_b    = (const float*)d_in[5];
    const float* x_proj_w  = (const float*)d_in[6];
    const float* dt_proj_w = (const float*)d_in[7];
    const float* dt_proj_b = (const float*)d_in[8];
    const float* A_log     = (const float*)d_in[9];
    const float* Dp        = (const float*)d_in[10];
    const float* out_pw    = (const float*)d_in[11];
    float* out = (float*)d_out;

    float *xdbl, *delta, *Ac, *Hc, *Ci;
    uint32_t *xn16, *xz16, *uconv16, *dt16, *win16, *wx16, *wdt16, *wout16;
    __nv_bfloat16* y16;
    cudaGetSymbolAddress((void**)&xdbl,    g_xdbl);
    cudaGetSymbolAddress((void**)&delta,   g_delta);
    cudaGetSymbolAddress((void**)&xn16,    g_xn16);
    cudaGetSymbolAddress((void**)&xz16,    g_xz16);
    cudaGetSymbolAddress((void**)&uconv16, g_uconv16);
    cudaGetSymbolAddress((void**)&dt16,    g_dt16);
    cudaGetSymbolAddress((void**)&y16,     g_y16);
    cudaGetSymbolAddress((void**)&win16,   g_win16);
    cudaGetSymbolAddress((void**)&wx16,    g_wx16);
    cudaGetSymbolAddress((void**)&wdt16,   g_wdt16);
    cudaGetSymbolAddress((void**)&wout16,  g_wout16);
    cudaGetSymbolAddress((void**)&Ac,      g_Ac);
    cudaGetSymbolAddress((void**)&Hc,      g_Hc);
    cudaGetSymbolAddress((void**)&Ci,      g_Ci);

    // 0. fused weight conversion
    {
        int tot = CN1 + CN2 + CN3 + CN4;
        convert_all<<<(tot + 255) / 256, 256>>>(
            in_proj_w, x_proj_w, dt_proj_w, out_pw, win16, wx16, wdt16, wout16);
    }

    // 1. LayerNorm -> xn16
    ln_kernel<<<MTOK, 256>>>(x, ln_w, ln_b, xn16);

    // 2. in_proj -> xz16 (bf16)
    gemm_lm<128, 128, 2, 4, 4><<<dim3((2 * DI) / 128, MTOK / 128), 256>>>(
        xn16, DM / 2, win16, DM / 2, nullptr, 0, DM, nullptr, xz16, 2 * DI / 2);

    // 3. conv + SiLU -> uconv16
    conv_silu_kernel<<<(MTOK * DI / 2 + 255) / 256, 256>>>(
        xz16, conv_w, conv_b, uconv16);

    // 4. x_proj -> xdbl fp32 (+ dt16)
    gemm_lm<32, 96, 2, 3, 3><<<dim3(1, MTOK / 32), 192>>>(
        uconv16, DI / 2, wx16, DI / 2, xdbl, XDBL_W, DI, nullptr, dt16, DTR / 2);

    // 5. dt_proj -> delta fp32
    gemm_lm<128, 128, 2, 4, 1><<<dim3(DI / 128, MTOK / 128), 256>>>(
        dt16, DTR / 2, wdt16, DTR / 2, delta, DI, DTR, dt_proj_b, nullptr, 0);

    // 6. chunked selective scan -> y16
    {
        int nw = BB * (DI / 2) * GCH;            // 32768 warps
        scan_p1<<<(nw * 32) / 256, 256>>>(delta, uconv16, xdbl, A_log, Ac, Hc);
        scan_p2<<<(BB * DI * DS + 255) / 256, 256>>>(Ac, Hc, Ci);
        scan_p3<<<(nw * 32) / 256, 256>>>(delta, uconv16, xdbl, xz16,
                                          A_log, Dp, Ci, y16);
    }

    // 7. out_proj + residual -> out
    gemm_lm<128, 128, 2, 4, 2><<<dim3(DM / 128, MTOK / 128), 256>>>(
        (const uint32_t*)y16, DI / 2, wout16, DI / 2, out, DM, DI, x, nullptr, 0);
}

// round 8
// speedup vs baseline: 6.5743x; 1.0461x over previous
#include <cuda_runtime.h>
#include <cuda_bf16.h>
#include <math.h>
#include <stdint.h>

// ---------------- problem constants ----------------
#define BB   2
#define LL   2048
#define DM   1024
#define DI   2048
#define DTR  64
#define DS   16
#define MTOK (BB * LL)   // 4096 tokens
#define XDBL_W 96
#define GCH  16          // scan chunks
#define CHLEN (LL / GCH) // 128
#define XKSPLIT 4

// ---------------- scratch ----------------
__device__ float    g_xdbl [(size_t)MTOK * XDBL_W];
__device__ float    g_delta[(size_t)MTOK * DI];
__device__ float    g_xpart[(size_t)XKSPLIT * MTOK * XDBL_W];
__device__ uint32_t g_xn16   [(size_t)MTOK * DM / 2];
__device__ uint32_t g_xz16   [(size_t)MTOK * 2 * DI / 2];   // u|z bf16 packed
__device__ uint32_t g_uconv16[(size_t)MTOK * DI / 2];
__device__ uint32_t g_dt16   [(size_t)MTOK * DTR / 2];
__device__ __nv_bfloat16 g_y16[(size_t)MTOK * DI];
__device__ uint32_t g_win16  [(size_t)2 * DI * DM / 2];
__device__ uint32_t g_wx16   [(size_t)XDBL_W * DI / 2];
__device__ uint32_t g_wdt16  [(size_t)DI * DTR / 2];
__device__ uint32_t g_wout16 [(size_t)DM * DI / 2];
// scan carries: [(b*DI+dd)*DS+n][GCH]
__device__ float g_Ac[(size_t)BB * DI * DS * GCH];
__device__ float g_Hc[(size_t)BB * DI * DS * GCH];
__device__ float g_Ci[(size_t)BB * DI * DS * GCH];

// ---------------- helpers ----------------
__device__ __forceinline__ float softplus_f(float v) {
    return (v > 20.f) ? v : log1pf(__expf(v));
}
__device__ __forceinline__ float silu_f(float v) {
    return v * (1.f / (1.f + __expf(-v)));
}
__device__ __forceinline__ uint32_t packbf(float lo, float hi) {
    __nv_bfloat162 h(__float2bfloat16_rn(lo), __float2bfloat16_rn(hi));
    return *reinterpret_cast<uint32_t*>(&h);
}
__device__ __forceinline__ float2 unpk(uint32_t v) {
    __nv_bfloat162 h = *reinterpret_cast<__nv_bfloat162*>(&v);
    return make_float2(__bfloat162float(h.x), __bfloat162float(h.y));
}
__device__ __forceinline__ void mma_bf16(float* c, const uint32_t* a, const uint32_t* b) {
    asm volatile("mma.sync.aligned.m16n8k16.row.col.f32.bf16.bf16.f32 "
                 "{%0,%1,%2,%3}, {%4,%5,%6,%7}, {%8,%9}, {%0,%1,%2,%3};"
                 : "+f"(c[0]), "+f"(c[1]), "+f"(c[2]), "+f"(c[3])
                 : "r"(a[0]), "r"(a[1]), "r"(a[2]), "r"(a[3]),
                   "r"(b[0]), "r"(b[1]));
}
__device__ __forceinline__ void cp16(void* dst, const void* src) {
    uint32_t d = (uint32_t)__cvta_generic_to_shared(dst);
    asm volatile("cp.async.cg.shared.global [%0], [%1], 16;" :: "r"(d), "l"(src));
}
__device__ __forceinline__ uint32_t smem_u32(const void* p) {
    uint32_t a;
    asm("{ .reg .u64 t; cvta.to.shared.u64 t, %1; cvt.u32.u64 %0, t; }"
        : "=r"(a) : "l"(p));
    return a;
}
__device__ __forceinline__ void ldm_x4(uint32_t* r, uint32_t addr) {
    asm volatile("ldmatrix.sync.aligned.m8n8.x4.shared.b16 {%0,%1,%2,%3}, [%4];"
        : "=r"(r[0]), "=r"(r[1]), "=r"(r[2]), "=r"(r[3]) : "r"(addr));
}

// ---------------- one fused weight conversion ----------------
#define CN1 (2 * DI * DM / 2)
#define CN2 (XDBL_W * DI / 2)
#define CN3 (DI * DTR / 2)
#define CN4 (DM * DI / 2)
__global__ void convert_all(const float* __restrict__ w1, const float* __restrict__ w2,
                            const float* __restrict__ w3, const float* __restrict__ w4,
                            uint32_t* __restrict__ d1, uint32_t* __restrict__ d2,
                            uint32_t* __restrict__ d3, uint32_t* __restrict__ d4) {
    int i = blockIdx.x * blockDim.x + threadIdx.x;
    const float2* s; uint32_t* d; int j;
    if (i < CN1)                      { s = (const float2*)w1; d = d1; j = i; }
    else if (i < CN1 + CN2)           { s = (const float2*)w2; d = d2; j = i - CN1; }
    else if (i < CN1 + CN2 + CN3)     { s = (const float2*)w3; d = d3; j = i - CN1 - CN2; }
    else if (i < CN1 + CN2 + CN3 + CN4){ s = (const float2*)w4; d = d4; j = i - CN1 - CN2 - CN3; }
    else return;
    float2 v = s[j];
    d[j] = packbf(v.x, v.y);
}

// ---------------- LayerNorm -> bf16 packed ----------------
__global__ void ln_kernel(const float* __restrict__ x,
                          const float* __restrict__ w,
                          const float* __restrict__ b,
                          uint32_t* __restrict__ out16) {
    const int row = blockIdx.x;
    const int tid = threadIdx.x;
    const float4* xr = (const float4*)(x + (size_t)row * DM);
    float4 v = xr[tid];

    float s  = v.x + v.y + v.z + v.w;
    float s2 = v.x * v.x + v.y * v.y + v.z * v.z + v.w * v.w;

    __shared__ float shs[8], shs2[8];
    #pragma unroll
    for (int o = 16; o > 0; o >>= 1) {
        s  += __shfl_down_sync(0xffffffffu, s,  o);
        s2 += __shfl_down_sync(0xffffffffu, s2, o);
    }
    if ((tid & 31) == 0) { shs[tid >> 5] = s; shs2[tid >> 5] = s2; }
    __syncthreads();
    float mu = 0.f, m2 = 0.f;
    #pragma unroll
    for (int i = 0; i < 8; i++) { mu += shs[i]; m2 += shs2[i]; }
    mu *= (1.f / DM);
    m2 *= (1.f / DM);
    float inv = rsqrtf(m2 - mu * mu + 1e-5f);

    float4 wv = ((const float4*)w)[tid];
    float4 bv = ((const float4*)b)[tid];
    uint2 p;
    p.x = packbf((v.x - mu) * inv * wv.x + bv.x, (v.y - mu) * inv * wv.y + bv.y);
    p.y = packbf((v.z - mu) * inv * wv.z + bv.z, (v.w - mu) * inv * wv.w + bv.w);
    ((uint2*)(out16 + (size_t)row * (DM / 2)))[tid] = p;
}

// ---------------- bf16 mma.sync GEMM (ldmatrix, optional split-K) -----------
// C[M,N] = A[M,K] @ W[N,K]^T. Packed bf16 inputs, lda in uint32 units.
// blockIdx.z selects a K slice: A,W advance kSliceU uint32; C advances cSliceF.
// EPI: 0 plain fp32, 1 softplus(v+aux[n]), 2 v+aux[m*ldc+n], 4 bf16-only -> Cb
template<int BM, int BN, int WM, int WN, int EPI>
__global__ __launch_bounds__(WM * WN * 32)
void gemm_lm(const uint32_t* __restrict__ A, int ldaU,
             const uint32_t* __restrict__ W, int ldwU,
             float* __restrict__ C, int ldc, int K,
             const float* __restrict__ aux,
             uint32_t* __restrict__ Cb, int ldcbU,
             int kSliceU, size_t cSliceF) {
    constexpr int NTHR = WM * WN * 32;
    constexpr int BK2 = 16;
    constexpr int STR = 20;
    constexpr int S = 3;
    constexpr int WARP_M = BM / WM;
    constexpr int WARP_N = BN / WN;
    constexpr int MT = WARP_M / 16;
    constexpr int NT = WARP_N / 8;
    static_assert(NT % 2 == 0, "NT must be even for x4 B loads");

    __shared__ __align__(16) uint32_t As[S][BM][STR];
    __shared__ __align__(16) uint32_t Bs[S][BN][STR];

    const int kz = blockIdx.z;
    A += (size_t)kz * kSliceU;
    W += (size_t)kz * kSliceU;
    C += (size_t)kz * cSliceF;

    const int tid  = threadIdx.x;
    const int lane = tid & 31;
    const int warp = tid >> 5;
    const int gid  = lane >> 2;
    const int tig  = lane & 3;

    const int bm0 = blockIdx.y * BM;
    const int bn0 = blockIdx.x * BN;
    const int wm0 = (warp / WN) * WARP_M;
    const int wn0 = (warp % WN) * WARP_N;

    float acc[MT][NT][4];
    #pragma unroll
    for (int i = 0; i < MT; i++)
        #pragma unroll
        for (int j = 0; j < NT; j++)
            #pragma unroll
            for (int e = 0; e < 4; e++) acc[i][j][e] = 0.f;

    auto load_tile = [&](int buf, int kt) {
        const int k0 = kt * BK2;
        #pragma unroll
        for (int s = tid; s < BM * 4; s += NTHR) {
            int r = s >> 2, c = (s & 3) * 4;
            cp16(&As[buf][r][c], A + (size_t)(bm0 + r) * ldaU + k0 + c);
        }
        #pragma unroll
        for (int s = tid; s < BN * 4; s += NTHR) {
            int r = s >> 2, c = (s & 3) * 4;
            cp16(&Bs[buf][r][c], W + (size_t)(bn0 + r) * ldwU + k0 + c);
        }
        asm volatile("cp.async.commit_group;");
    };

    const int nkt = K / 32;
    load_tile(0, 0);
    if (nkt > 1) load_tile(1, 1);

    const uint32_t a_row = (uint32_t)(lane & 15);
    const uint32_t a_col = (uint32_t)((lane >> 4) << 2);
    const uint32_t b_row = (uint32_t)((lane & 7) + ((lane >> 4) << 3));
    const uint32_t b_col = (uint32_t)(((lane >> 3) & 1) << 2);

    for (int kt = 0; kt < nkt; kt++) {
        const int buf = kt % S;
        if (kt + 1 < nkt) asm volatile("cp.async.wait_group 1;");
        else              asm volatile("cp.async.wait_group 0;");
        __syncthreads();
        if (kt + 2 < nkt) load_tile((kt + 2) % S, kt + 2);

        const uint32_t abase = smem_u32(&As[buf][0][0]);
        const uint32_t bbase = smem_u32(&Bs[buf][0][0]);

        #pragma unroll
        for (int ks = 0; ks < 2; ks++) {
            uint32_t af[MT][4];
            uint32_t bf[NT][2];
            #pragma unroll
            for (int mt = 0; mt < MT; mt++) {
                uint32_t r = (uint32_t)(wm0 + mt * 16) + a_row;
                ldm_x4(af[mt], abase + (r * STR + ks * 8 + a_col) * 4);
            }
            #pragma unroll
            for (int ip = 0; ip < NT / 2; ip++) {
                uint32_t r = (uint32_t)(wn0 + ip * 16) + b_row;
                uint32_t q[4];
                ldm_x4(q, bbase + (r * STR + ks * 8 + b_col) * 4);
                bf[2 * ip][0]     = q[0]; bf[2 * ip][1]     = q[1];
                bf[2 * ip + 1][0] = q[2]; bf[2 * ip + 1][1] = q[3];
            }
            #pragma unroll
            for (int mt = 0; mt < MT; mt++)
                #pragma unroll
                for (int nt = 0; nt < NT; nt++)
                    mma_bf16(acc[mt][nt], af[mt], bf[nt]);
        }
    }

    #pragma unroll
    for (int mt = 0; mt < MT; mt++) {
        int r0 = bm0 + wm0 + mt * 16 + gid;
        int r1 = r0 + 8;
        #pragma unroll
        for (int nt = 0; nt < NT; nt++) {
            int cn = bn0 + wn0 + nt * 8 + 2 * tig;
            float v0 = acc[mt][nt][0], v1 = acc[mt][nt][1];
            float v2 = acc[mt][nt][2], v3 = acc[mt][nt][3];
            if (EPI == 4) {
                Cb[(size_t)r0 * ldcbU + cn / 2] = packbf(v0, v1);
                Cb[(size_t)r1 * ldcbU + cn / 2] = packbf(v2, v3);
                continue;
            }
            if (EPI == 1) {
                v0 = softplus_f(v0 + aux[cn]);   v1 = softplus_f(v1 + aux[cn + 1]);
                v2 = softplus_f(v2 + aux[cn]);   v3 = softplus_f(v3 + aux[cn + 1]);
            }
            if (EPI == 2) {
                v0 += aux[(size_t)r0 * ldc + cn];  v1 += aux[(size_t)r0 * ldc + cn + 1];
                v2 += aux[(size_t)r1 * ldc + cn];  v3 += aux[(size_t)r1 * ldc + cn + 1];
            }
            *(float2*)(C + (size_t)r0 * ldc + cn) = make_float2(v0, v1);
            *(float2*)(C + (size_t)r1 * ldc + cn) = make_float2(v2, v3);
        }
    }
}

// ---------------- x_proj split-K reduce: partials -> xdbl + dt16 ------------
__global__ void xproj_reduce(const float* __restrict__ parts,
                             float* __restrict__ xdbl,
                             uint32_t* __restrict__ dt16) {
    int idx = blockIdx.x * blockDim.x + threadIdx.x;     // float2 index
    if (idx >= MTOK * XDBL_W / 2) return;
    float2 s = make_float2(0.f, 0.f);
    #pragma unroll
    for (int z = 0; z < XKSPLIT; z++) {
        float2 v = ((const float2*)(parts + (size_t)z * MTOK * XDBL_W))[idx];
        s.x += v.x; s.y += v.y;
    }
    ((float2*)xdbl)[idx] = s;
    int col2 = idx % (XDBL_W / 2);
    if (col2 < DTR / 2) {
        int row = idx / (XDBL_W / 2);
        dt16[(size_t)row * (DTR / 2) + col2] = packbf(s.x, s.y);
    }
}

// ---------------- causal conv(4) + bias + SiLU (bf16 in/out) ---------------
__global__ void conv_silu_kernel(const uint32_t* __restrict__ xz16,
                                 const float* __restrict__ cw,
                                 const float* __restrict__ cb,
                                 uint32_t* __restrict__ out16) {
    int idx = blockIdx.x * blockDim.x + threadIdx.x;
    if (idx >= MTOK * DI / 2) return;
    int dp = idx % (DI / 2);
    int d  = dp * 2;
    int t  = idx / (DI / 2);
    int l  = t % LL;

    const uint32_t* up = xz16 + (size_t)t * (2 * DI / 2) + dp;
    float2 c0 = unpk(up[0]);
    float2 c1 = (l >= 1) ? unpk(up[-(2 * DI / 2) * 1]) : make_float2(0.f, 0.f);
    float2 c2 = (l >= 2) ? unpk(up[-(2 * DI / 2) * 2]) : make_float2(0.f, 0.f);
    float2 c3 = (l >= 3) ? unpk(up[-(2 * DI / 2) * 3]) : make_float2(0.f, 0.f);

    float4 wA = *(const float4*)(cw + (size_t)d * 4);
    float4 wB = *(const float4*)(cw + (size_t)(d + 1) * 4);
    float r0 = silu_f(wA.w * c0.x + wA.z * c1.x + wA.y * c2.x + wA.x * c3.x + cb[d]);
    float r1 = silu_f(wB.w * c0.y + wB.z * c1.y + wB.y * c2.y + wB.x * c3.y + cb[d + 1]);
    out16[idx] = packbf(r0, r1);
}

// ---------------- chunked selective scan ------------------------------------
__global__ void scan_p1(const float* __restrict__ delta,
                        const uint32_t* __restrict__ u16,
                        const float* __restrict__ xdbl,
                        const float* __restrict__ A_log,
                        float* __restrict__ gAc, float* __restrict__ gHc) {
    int gt   = blockIdx.x * blockDim.x + threadIdx.x;
    int w    = gt >> 5;
    int lane = gt & 31;
    if (w >= BB * (DI / 2) * GCH) return;

    int pair = w & 1023;
    int b    = (w >> 10) & 1;
    int g    = w >> 11;
    int hi   = lane >> 4;
    int dd   = pair * 2 + hi;
    int n    = lane & 15;
    int t0   = g * CHLEN;

    float Ad = -expf(A_log[dd * DS + n]);
    float h = 0.f, ap = 1.f;

    const size_t base_d = (size_t)(b * LL + t0) * DI + dd;
    const size_t base_u = (size_t)(b * LL + t0) * (DI / 2) + pair;
    const size_t base_x = (size_t)(b * LL + t0) * XDBL_W;

    constexpr int U = 4;
    float de[U], Bn[U];
    uint32_t uup[U];
    #pragma unroll
    for (int j = 0; j < U; j++) {
        de[j]  = delta[base_d + (size_t)j * DI];
        uup[j] = u16 [base_u + (size_t)j * (DI / 2)];
        Bn[j]  = xdbl[base_x + (size_t)j * XDBL_W + DTR + n];
    }
    for (int t = 0; t < CHLEN; t += U) {
        float cde[U], cBn[U], cuu[U];
        #pragma unroll
        for (int j = 0; j < U; j++) {
            cde[j] = de[j]; cBn[j] = Bn[j];
            float2 uv = unpk(uup[j]);
            cuu[j] = hi ? uv.y : uv.x;
        }
        if (t + U < CHLEN) {
            const size_t od = base_d + (size_t)(t + U) * DI;
            const size_t ou = base_u + (size_t)(t + U) * (DI / 2);
            const size_t ox = base_x + (size_t)(t + U) * XDBL_W;
            #pragma unroll
            for (int j = 0; j < U; j++) {
                de[j]  = delta[od + (size_t)j * DI];
                uup[j] = u16 [ou + (size_t)j * (DI / 2)];
                Bn[j]  = xdbl[ox + (size_t)j * XDBL_W + DTR + n];
            }
        }
        #pragma unroll
        for (int j = 0; j < U; j++) {
            float dA = __expf(cde[j] * Ad);
            h = fmaf(dA, h, cde[j] * cuu[j] * cBn[j]);
            ap *= dA;
        }
    }
    size_t idx = ((size_t)(b * DI + dd) * DS + n) * GCH + g;
    gAc[idx] = ap;
    gHc[idx] = h;
}

__global__ void scan_p2(const float* __restrict__ gAc,
                        const float* __restrict__ gHc,
                        float* __restrict__ gCi) {
    int i = blockIdx.x * blockDim.x + threadIdx.x;
    if (i >= BB * DI * DS) return;
    size_t base = (size_t)i * GCH;
    float c = 0.f;
    #pragma unroll
    for (int g = 0; g < GCH; g++) {
        gCi[base + g] = c;
        c = fmaf(gAc[base + g], c, gHc[base + g]);
    }
}

__global__ void scan_p3(const float* __restrict__ delta,
                        const uint32_t* __restrict__ u16,
                        const float* __restrict__ xdbl,
                        const uint32_t* __restrict__ xz16,
                        const float* __restrict__ A_log,
                        const float* __restrict__ Dp,
                        const float* __restrict__ gCi,
                        __nv_bfloat16* __restrict__ y16) {
    int gt   = blockIdx.x * blockDim.x + threadIdx.x;
    int w    = gt >> 5;
    int lane = gt & 31;
    if (w >= BB * (DI / 2) * GCH) return;

    int pair = w & 1023;
    int b    = (w >> 10) & 1;
    int g    = w >> 11;
    int hi   = lane >> 4;
    int dd   = pair * 2 + hi;
    int n    = lane & 15;
    int t0   = g * CHLEN;

    float Ad = -expf(A_log[dd * DS + n]);
    float Dd = Dp[dd];
    float h  = gCi[((size_t)(b * DI + dd) * DS + n) * GCH + g];

    const size_t base_d = (size_t)(b * LL + t0) * DI + dd;
    const size_t base_u = (size_t)(b * LL + t0) * (DI / 2) + pair;
    const size_t base_x = (size_t)(b * LL + t0) * XDBL_W;
    const size_t base_z = (size_t)(b * LL + t0) * (2 * DI / 2) + DI / 2 + pair;

    constexpr int U = 4;
    float de[U], Bn[U], Cn[U];
    uint32_t uup[U], zzp[U];
    #pragma unroll
    for (int j = 0; j < U; j++) {
        de[j]  = delta[base_d + (size_t)j * DI];
        uup[j] = u16 [base_u + (size_t)j * (DI / 2)];
        Bn[j]  = xdbl[base_x + (size_t)j * XDBL_W + DTR + n];
        Cn[j]  = xdbl[base_x + (size_t)j * XDBL_W + DTR + DS + n];
        zzp[j] = xz16[base_z + (size_t)j * (2 * DI / 2)];
    }
    for (int t = 0; t < CHLEN; t += U) {
        float cde[U], cBn[U], cCn[U], cuu[U], czv[U];
        #pragma unroll
        for (int j = 0; j < U; j++) {
            cde[j] = de[j]; cBn[j] = Bn[j]; cCn[j] = Cn[j];
            float2 uv = unpk(uup[j]);
            float2 zv2 = unpk(zzp[j]);
            cuu[j] = hi ? uv.y : uv.x;
            czv[j] = hi ? zv2.y : zv2.x;
        }
        if (t + U < CHLEN) {
            const size_t od = base_d + (size_t)(t + U) * DI;
            const size_t ou = base_u + (size_t)(t + U) * (DI / 2);
            const size_t ox = base_x + (size_t)(t + U) * XDBL_W;
            const size_t oz = base_z + (size_t)(t + U) * (2 * DI / 2);
            #pragma unroll
            for (int j = 0; j < U; j++) {
                de[j]  = delta[od + (size_t)j * DI];
                uup[j] = u16 [ou + (size_t)j * (DI / 2)];
                Bn[j]  = xdbl[ox + (size_t)j * XDBL_W + DTR + n];
                Cn[j]  = xdbl[ox + (size_t)j * XDBL_W + DTR + DS + n];
                zzp[j] = xz16[oz + (size_t)j * (2 * DI / 2)];
            }
        }
        float yv[U];
        #pragma unroll
        for (int j = 0; j < U; j++) {
            float dA = __expf(cde[j] * Ad);
            h = fmaf(dA, h, cde[j] * cuu[j] * cBn[j]);
            yv[j] = h * cCn[j];
        }
        #pragma unroll
        for (int o = 8; o > 0; o >>= 1) {
            #pragma unroll
            for (int j = 0; j < U; j++)
                yv[j] += __shfl_xor_sync(0xffffffffu, yv[j], o);
        }
        if (n == 0) {
            #pragma unroll
            for (int j = 0; j < U; j++)
                y16[base_d + (size_t)(t + j) * DI] =
                    __float2bfloat16_rn((yv[j] + cuu[j] * Dd) * silu_f(czv[j]));
        }
    }
}

// ---------------- launch ----------------------------------------------------
extern "C" void kernel_launch(void* const* d_in, const int* in_sizes, int n_in,
                              void* d_out, int out_size) {
    const float* x         = (const float*)d_in[0];
    const float* ln_w      = (const float*)d_in[1];
    const float* ln_b      = (const float*)d_in[2];
    const float* in_proj_w = (const float*)d_in[3];
    const float* conv_w    = (const float*)d_in[4];
    const float* conv_b    = (const float*)d_in[5];
    const float* x_proj_w  = (const float*)d_in[6];
    const float* dt_proj_w = (const float*)d_in[7];
    const float* dt_proj_b = (const float*)d_in[8];
    const float* A_log     = (const float*)d_in[9];
    const float* Dp        = (const float*)d_in[10];
    const float* out_pw    = (const float*)d_in[11];
    float* out = (float*)d_out;

    float *xdbl, *delta, *xpart, *Ac, *Hc, *Ci;
    uint32_t *xn16, *xz16, *uconv16, *dt16, *win16, *wx16, *wdt16, *wout16;
    __nv_bfloat16* y16;
    cudaGetSymbolAddress((void**)&xdbl,    g_xdbl);
    cudaGetSymbolAddress((void**)&delta,   g_delta);
    cudaGetSymbolAddress((void**)&xpart,   g_xpart);
    cudaGetSymbolAddress((void**)&xn16,    g_xn16);
    cudaGetSymbolAddress((void**)&xz16,    g_xz16);
    cudaGetSymbolAddress((void**)&uconv16, g_uconv16);
    cudaGetSymbolAddress((void**)&dt16,    g_dt16);
    cudaGetSymbolAddress((void**)&y16,     g_y16);
    cudaGetSymbolAddress((void**)&win16,   g_win16);
    cudaGetSymbolAddress((void**)&wx16,    g_wx16);
    cudaGetSymbolAddress((void**)&wdt16,   g_wdt16);
    cudaGetSymbolAddress((void**)&wout16,  g_wout16);
    cudaGetSymbolAddress((void**)&Ac,      g_Ac);
    cudaGetSymbolAddress((void**)&Hc,      g_Hc);
    cudaGetSymbolAddress((void**)&Ci,      g_Ci);

    // 0. fused weight conversion
    {
        int tot = CN1 + CN2 + CN3 + CN4;
        convert_all<<<(tot + 255) / 256, 256>>>(
            in_proj_w, x_proj_w, dt_proj_w, out_pw, win16, wx16, wdt16, wout16);
    }

    // 1. LayerNorm -> xn16
    ln_kernel<<<MTOK, 256>>>(x, ln_w, ln_b, xn16);

    // 2. in_proj -> xz16 (bf16), 64x64 warp tile
    gemm_lm<128, 128, 2, 2, 4><<<dim3((2 * DI) / 128, MTOK / 128), 128>>>(
        xn16, DM / 2, win16, DM / 2, nullptr, 0, DM, nullptr,
        xz16, 2 * DI / 2, 0, 0);

    // 3. conv + SiLU -> uconv16
    conv_silu_kernel<<<(MTOK * DI / 2 + 255) / 256, 256>>>(
        xz16, conv_w, conv_b, uconv16);

    // 4. x_proj split-K=4 -> partials; reduce -> xdbl fp32 + dt16
    gemm_lm<32, 96, 2, 3, 0><<<dim3(1, MTOK / 32, XKSPLIT), 192>>>(
        uconv16, DI / 2, wx16, DI / 2, xpart, XDBL_W, DI / XKSPLIT, nullptr,
        nullptr, 0, (DI / XKSPLIT) / 2, (size_t)MTOK * XDBL_W);
    xproj_reduce<<<(MTOK * XDBL_W / 2 + 255) / 256, 256>>>(xpart, xdbl, dt16);

    // 5. dt_proj -> delta fp32, 64x64 warp tile
    gemm_lm<128, 128, 2, 2, 1><<<dim3(DI / 128, MTOK / 128), 128>>>(
        dt16, DTR / 2, wdt16, DTR / 2, delta, DI, DTR, dt_proj_b,
        nullptr, 0, 0, 0);

    // 6. chunked selective scan -> y16
    {
        int nw = BB * (DI / 2) * GCH;
        scan_p1<<<(nw * 32) / 256, 256>>>(delta, uconv16, xdbl, A_log, Ac, Hc);
        scan_p2<<<(BB * DI * DS + 255) / 256, 256>>>(Ac, Hc, Ci);
        scan_p3<<<(nw * 32) / 256, 256>>>(delta, uconv16, xdbl, xz16,
                                          A_log, Dp, Ci, y16);
    }

    // 7. out_proj + residual -> out, 64x64 warp tile
    gemm_lm<128, 128, 2, 2, 2><<<dim3(DM / 128, MTOK / 128), 128>>>(
        (const uint32_t*)y16, DI / 2, wout16, DI / 2, out, DM, DI, x,
        nullptr, 0, 0, 0);
}